// round 6
// baseline (speedup 1.0000x reference)
#include <cuda_runtime.h>
#include <cuda_bf16.h>
#include <math.h>

// ---------------- problem constants ----------------
#define BATCH   2
#define IMG     96
#define PP      8
#define EMB     384
#define NH      8
#define HD      48
#define NL      6
#define MLPD    1536
#define NC      2
#define NPATCH  1728            // (96/8)^3
#define NTOK    1729            // NPATCH + 1
#define PK      512             // P^3 * CIN
#define QKVD    1152            // 3*EMB

// ---------------- device scratch (static, allocation-free) ----------------
__device__ float g_patches[BATCH * NPATCH * PK];      // 7.1 MB
__device__ float g_t     [BATCH * NTOK * EMB];        // 5.3 MB  tokens (residual stream)
__device__ float g_h     [BATCH * NTOK * EMB];        // 5.3 MB  LN output
__device__ float g_qkv   [BATCH * NTOK * QKVD];       // 15.9 MB
__device__ float g_attno [BATCH * NTOK * EMB];        // 5.3 MB
__device__ float g_mlp   [BATCH * NTOK * MLPD];       // 21.2 MB

// ---------------- patchify: gather 8x8x8 patches into GEMM rows ----------------
__global__ void patchify_kernel(const float* __restrict__ x) {
    int gid = blockIdx.x * blockDim.x + threadIdx.x;
    const int total = BATCH * NPATCH * PK;
    if (gid >= total) return;
    int e = gid & (PK - 1);         // 0..511
    int r = gid >> 9;               // patch row
    int b = r / NPATCH;
    int p = r - b * NPATCH;
    int pz = p / 144;
    int py = (p / 12) % 12;
    int px = p % 12;
    int i = e >> 6;                 // 0..7
    int j = (e >> 3) & 7;
    int k = e & 7;
    size_t src = (size_t)b * IMG * IMG * IMG
               + (size_t)(pz * PP + i) * IMG * IMG
               + (size_t)(py * PP + j) * IMG
               + (px * PP + k);
    g_patches[(size_t)r * PK + e] = x[src];
}

// ---------------- cls token + pos embed row 0 ----------------
__global__ void cls_init_kernel(const float* __restrict__ cls_token,
                                const float* __restrict__ pos_embed) {
    int gid = blockIdx.x * blockDim.x + threadIdx.x;
    if (gid >= BATCH * EMB) return;
    int b = gid / EMB;
    int e = gid - b * EMB;
    g_t[(size_t)b * NTOK * EMB + e] = cls_token[e] + pos_embed[e];
}

// ---------------- generic fp32 GEMM:  C[M,N] = A[M,K] * W[N,K]^T  ----------------
// EPI: 0 = bias store, 1 = bias + exact GELU, 2 = bias + residual add into C,
//      3 = patch embed: bias + pos_embed, scattered into token buffer
#define BM 64
#define BN 64
#define BK 16

template<int EPI>
__global__ void gemm_kernel(const float* __restrict__ A, const float* __restrict__ W,
                            const float* __restrict__ bias, float* __restrict__ C,
                            int M, int N, int K, const float* __restrict__ extra) {
    __shared__ float As[BK][BM];
    __shared__ float Ws[BK][BN];
    const int tid = threadIdx.x;           // 256 threads
    const int tx = tid & 15;
    const int ty = tid >> 4;
    const int bm = blockIdx.y * BM;
    const int bn = blockIdx.x * BN;

    float acc[4][4] = {};

    for (int k0 = 0; k0 < K; k0 += BK) {
        #pragma unroll
        for (int l = 0; l < 4; l++) {
            int idx = tid + l * 256;       // 0..1023
            int mn = idx >> 4;             // 0..63
            int kk = idx & 15;
            int row = bm + mn;
            As[kk][mn] = (row < M) ? A[(size_t)row * K + k0 + kk] : 0.f;
            Ws[kk][mn] = W[(size_t)(bn + mn) * K + k0 + kk];
        }
        __syncthreads();
        #pragma unroll
        for (int kk = 0; kk < BK; kk++) {
            float4 a = *reinterpret_cast<const float4*>(&As[kk][ty * 4]);
            float4 w = *reinterpret_cast<const float4*>(&Ws[kk][tx * 4]);
            float av[4] = {a.x, a.y, a.z, a.w};
            float wv[4] = {w.x, w.y, w.z, w.w};
            #pragma unroll
            for (int i = 0; i < 4; i++)
                #pragma unroll
                for (int j = 0; j < 4; j++)
                    acc[i][j] += av[i] * wv[j];
        }
        __syncthreads();
    }

    #pragma unroll
    for (int i = 0; i < 4; i++) {
        int row = bm + ty * 4 + i;
        if (row >= M) continue;
        #pragma unroll
        for (int j = 0; j < 4; j++) {
            int col = bn + tx * 4 + j;
            float v = acc[i][j] + bias[col];
            if (EPI == 0) {
                C[(size_t)row * N + col] = v;
            } else if (EPI == 1) {
                // exact GELU: 0.5*x*(1+erf(x/sqrt(2)))
                C[(size_t)row * N + col] = 0.5f * v * (1.0f + erff(v * 0.70710678118654752f));
            } else if (EPI == 2) {
                size_t o = (size_t)row * N + col;
                C[o] = C[o] + v;
            } else { // EPI == 3: patch embed -> token buffer + pos_embed
                int b = row / NPATCH;
                int p = row - b * NPATCH;
                size_t o = ((size_t)b * NTOK + 1 + p) * EMB + col;
                C[o] = v + extra[(size_t)(1 + p) * EMB + col];
            }
        }
    }
}

// ---------------- LayerNorm over last dim (EMB) ----------------
__global__ void ln_kernel(const float* __restrict__ x, const float* __restrict__ w,
                          const float* __restrict__ bvec, float* __restrict__ y) {
    const int row = blockIdx.x;
    const float* xr = x + (size_t)row * EMB;
    const int tid = threadIdx.x;           // 128
    float s = 0.f, s2 = 0.f;
    #pragma unroll
    for (int e = tid; e < EMB; e += 128) {
        float v = xr[e];
        s += v; s2 += v * v;
    }
    #pragma unroll
    for (int o = 16; o; o >>= 1) {
        s  += __shfl_xor_sync(0xffffffffu, s,  o);
        s2 += __shfl_xor_sync(0xffffffffu, s2, o);
    }
    __shared__ float r1[4], r2[4];
    if ((tid & 31) == 0) { r1[tid >> 5] = s; r2[tid >> 5] = s2; }
    __syncthreads();
    float S  = r1[0] + r1[1] + r1[2] + r1[3];
    float S2 = r2[0] + r2[1] + r2[2] + r2[3];
    float mu = S * (1.0f / EMB);
    float var = S2 * (1.0f / EMB) - mu * mu;
    float rs = rsqrtf(var + 1e-5f);
    float* yr = y + (size_t)row * EMB;
    #pragma unroll
    for (int e = tid; e < EMB; e += 128)
        yr[e] = (xr[e] - mu) * rs * w[e] + bvec[e];
}

// ---------------- attention: one block per (b, h, query n) ----------------
#define ATT_T 128
__global__ void attn_kernel(const float* __restrict__ qkv, float* __restrict__ out) {
    const int n = blockIdx.x;
    const int h = blockIdx.y;
    const int b = blockIdx.z;
    __shared__ float sq[HD];
    __shared__ float ss[NTOK];
    __shared__ float sred[4];
    __shared__ float vred[4][HD];
    const int tid = threadIdx.x;

    const float* qp = qkv + ((size_t)(b * NTOK + n)) * QKVD + h * HD;
    if (tid < HD) sq[tid] = qp[tid];
    __syncthreads();

    const float scale = rsqrtf((float)HD);
    float lmax = -1e30f;
    for (int m = tid; m < NTOK; m += ATT_T) {
        const float* kp = qkv + ((size_t)(b * NTOK + m)) * QKVD + EMB + h * HD;
        float s = 0.f;
        #pragma unroll
        for (int d = 0; d < HD; d++) s += sq[d] * kp[d];
        s *= scale;
        ss[m] = s;
        lmax = fmaxf(lmax, s);
    }
    #pragma unroll
    for (int o = 16; o; o >>= 1) lmax = fmaxf(lmax, __shfl_xor_sync(0xffffffffu, lmax, o));
    if ((tid & 31) == 0) sred[tid >> 5] = lmax;
    __syncthreads();
    float gmax = fmaxf(fmaxf(sred[0], sred[1]), fmaxf(sred[2], sred[3]));
    __syncthreads();

    float lsum = 0.f;
    float acc[HD];
    #pragma unroll
    for (int d = 0; d < HD; d++) acc[d] = 0.f;
    for (int m = tid; m < NTOK; m += ATT_T) {
        float p = expf(ss[m] - gmax);
        lsum += p;
        const float* vp = qkv + ((size_t)(b * NTOK + m)) * QKVD + 2 * EMB + h * HD;
        #pragma unroll
        for (int d = 0; d < HD; d++) acc[d] += p * vp[d];
    }
    #pragma unroll
    for (int o = 16; o; o >>= 1) lsum += __shfl_xor_sync(0xffffffffu, lsum, o);
    if ((tid & 31) == 0) sred[tid >> 5] = lsum;
    #pragma unroll
    for (int d = 0; d < HD; d++)
        #pragma unroll
        for (int o = 16; o; o >>= 1) acc[d] += __shfl_xor_sync(0xffffffffu, acc[d], o);
    if ((tid & 31) == 0) {
        #pragma unroll
        for (int d = 0; d < HD; d++) vred[tid >> 5][d] = acc[d];
    }
    __syncthreads();
    if (tid < HD) {
        float gsum = sred[0] + sred[1] + sred[2] + sred[3];
        float r = (vred[0][tid] + vred[1][tid] + vred[2][tid] + vred[3][tid]) / gsum;
        out[((size_t)(b * NTOK + n)) * EMB + h * HD + tid] = r;
    }
}

// ---------------- final LN(row 0) + classification head ----------------
__global__ void head_kernel(const float* __restrict__ t, const float* __restrict__ nw,
                            const float* __restrict__ nb, const float* __restrict__ hw,
                            const float* __restrict__ hb, float* __restrict__ out) {
    const int b = blockIdx.x;
    const float* xr = t + (size_t)b * NTOK * EMB;   // token 0
    const int tid = threadIdx.x;                     // 128
    float s = 0.f, s2 = 0.f;
    for (int e = tid; e < EMB; e += 128) { float v = xr[e]; s += v; s2 += v * v; }
    #pragma unroll
    for (int o = 16; o; o >>= 1) {
        s  += __shfl_xor_sync(0xffffffffu, s,  o);
        s2 += __shfl_xor_sync(0xffffffffu, s2, o);
    }
    __shared__ float r1[4], r2[4], rd0[4], rd1[4];
    if ((tid & 31) == 0) { r1[tid >> 5] = s; r2[tid >> 5] = s2; }
    __syncthreads();
    float S  = r1[0] + r1[1] + r1[2] + r1[3];
    float S2 = r2[0] + r2[1] + r2[2] + r2[3];
    float mu = S * (1.0f / EMB);
    float rs = rsqrtf(S2 * (1.0f / EMB) - mu * mu + 1e-5f);
    float d0 = 0.f, d1 = 0.f;
    for (int e = tid; e < EMB; e += 128) {
        float nv = (xr[e] - mu) * rs * nw[e] + nb[e];
        d0 += nv * hw[e];
        d1 += nv * hw[EMB + e];
    }
    #pragma unroll
    for (int o = 16; o; o >>= 1) {
        d0 += __shfl_xor_sync(0xffffffffu, d0, o);
        d1 += __shfl_xor_sync(0xffffffffu, d1, o);
    }
    if ((tid & 31) == 0) { rd0[tid >> 5] = d0; rd1[tid >> 5] = d1; }
    __syncthreads();
    if (tid == 0) {
        out[b * NC + 0] = rd0[0] + rd0[1] + rd0[2] + rd0[3] + hb[0];
        out[b * NC + 1] = rd1[0] + rd1[1] + rd1[2] + rd1[3] + hb[1];
    }
}

// ---------------- host orchestration ----------------
extern "C" void kernel_launch(void* const* d_in, const int* in_sizes, int n_in,
                              void* d_out, int out_size) {
    const float* x         = (const float*)d_in[0];
    const float* conv_w    = (const float*)d_in[1];
    const float* conv_b    = (const float*)d_in[2];
    const float* cls_token = (const float*)d_in[3];
    const float* pos_embed = (const float*)d_in[4];
    const float* ln1_w     = (const float*)d_in[5];
    const float* ln1_b     = (const float*)d_in[6];
    const float* qkv_w     = (const float*)d_in[7];
    const float* qkv_b     = (const float*)d_in[8];
    const float* proj_w    = (const float*)d_in[9];
    const float* proj_b    = (const float*)d_in[10];
    const float* ln2_w     = (const float*)d_in[11];
    const float* ln2_b     = (const float*)d_in[12];
    const float* mlp_w1    = (const float*)d_in[13];
    const float* mlp_b1    = (const float*)d_in[14];
    const float* mlp_w2    = (const float*)d_in[15];
    const float* mlp_b2    = (const float*)d_in[16];
    const float* norm_w    = (const float*)d_in[17];
    const float* norm_b    = (const float*)d_in[18];
    const float* head_w    = (const float*)d_in[19];
    const float* head_b    = (const float*)d_in[20];
    float* out = (float*)d_out;

    float *patches, *t, *h, *qkv, *attno, *mlp;
    cudaGetSymbolAddress((void**)&patches, g_patches);
    cudaGetSymbolAddress((void**)&t,       g_t);
    cudaGetSymbolAddress((void**)&h,       g_h);
    cudaGetSymbolAddress((void**)&qkv,     g_qkv);
    cudaGetSymbolAddress((void**)&attno,   g_attno);
    cudaGetSymbolAddress((void**)&mlp,     g_mlp);

    const int Mtok = BATCH * NTOK;   // 3458
    const int Mpat = BATCH * NPATCH; // 3456

    // 1) patchify + patch-embed GEMM (scatter into token buffer with pos_embed)
    {
        int total = BATCH * NPATCH * PK;
        patchify_kernel<<<(total + 255) / 256, 256>>>(x);
        dim3 grid(EMB / BN, (Mpat + BM - 1) / BM);
        gemm_kernel<3><<<grid, 256>>>(patches, conv_w, conv_b, t, Mpat, EMB, PK, pos_embed);
        cls_init_kernel<<<(BATCH * EMB + 255) / 256, 256>>>(cls_token, pos_embed);
    }

    // 2) transformer layers
    for (int i = 0; i < NL; i++) {
        // LN1 -> h
        ln_kernel<<<Mtok, 128>>>(t, ln1_w + i * EMB, ln1_b + i * EMB, h);
        // qkv = h @ qkv_w^T + b
        {
            dim3 grid(QKVD / BN, (Mtok + BM - 1) / BM);
            gemm_kernel<0><<<grid, 256>>>(h, qkv_w + (size_t)i * QKVD * EMB,
                                          qkv_b + i * QKVD, qkv, Mtok, QKVD, EMB, nullptr);
        }
        // attention -> attno
        {
            dim3 grid(NTOK, NH, BATCH);
            attn_kernel<<<grid, ATT_T>>>(qkv, attno);
        }
        // t += attno @ proj_w^T + b
        {
            dim3 grid(EMB / BN, (Mtok + BM - 1) / BM);
            gemm_kernel<2><<<grid, 256>>>(attno, proj_w + (size_t)i * EMB * EMB,
                                          proj_b + i * EMB, t, Mtok, EMB, EMB, nullptr);
        }
        // LN2 -> h
        ln_kernel<<<Mtok, 128>>>(t, ln2_w + i * EMB, ln2_b + i * EMB, h);
        // mlp = gelu(h @ w1^T + b1)
        {
            dim3 grid(MLPD / BN, (Mtok + BM - 1) / BM);
            gemm_kernel<1><<<grid, 256>>>(h, mlp_w1 + (size_t)i * MLPD * EMB,
                                          mlp_b1 + i * MLPD, mlp, Mtok, MLPD, EMB, nullptr);
        }
        // t += mlp @ w2^T + b2
        {
            dim3 grid(EMB / BN, (Mtok + BM - 1) / BM);
            gemm_kernel<2><<<grid, 256>>>(mlp, mlp_w2 + (size_t)i * EMB * MLPD,
                                          mlp_b2 + i * EMB, t, Mtok, EMB, MLPD, nullptr);
        }
    }

    // 3) final LN on cls token + head
    head_kernel<<<BATCH, 128>>>(t, norm_w, norm_b, head_w, head_b, out);
}

// round 7
// speedup vs baseline: 1.0003x; 1.0003x over previous
#include <cuda_runtime.h>
#include <cuda_bf16.h>
#include <math.h>

// ---------------- problem constants ----------------
#define BATCH   2
#define IMG     96
#define PP      8
#define EMB     384
#define NH      8
#define HD      48
#define NL      6
#define MLPD    1536
#define NC      2
#define NPATCH  1728            // (96/8)^3
#define NTOK    1729            // NPATCH + 1
#define PK      512             // P^3 * CIN
#define QKVD    1152            // 3*EMB

// ---------------- device scratch (static, allocation-free) ----------------
__device__ float g_patches[BATCH * NPATCH * PK];      // 7.1 MB
__device__ float g_t     [BATCH * NTOK * EMB];        // 5.3 MB  tokens (residual stream)
__device__ float g_h     [BATCH * NTOK * EMB];        // 5.3 MB  LN output
__device__ float g_qkv   [BATCH * NTOK * QKVD];       // 15.9 MB
__device__ float g_attno [BATCH * NTOK * EMB];        // 5.3 MB
__device__ float g_mlp   [BATCH * NTOK * MLPD];       // 21.2 MB

// ---------------- patchify: gather 8x8x8 patches into GEMM rows ----------------
__global__ void patchify_kernel(const float* __restrict__ x) {
    int gid = blockIdx.x * blockDim.x + threadIdx.x;
    const int total = BATCH * NPATCH * PK;
    if (gid >= total) return;
    int e = gid & (PK - 1);         // 0..511
    int r = gid >> 9;               // patch row
    int b = r / NPATCH;
    int p = r - b * NPATCH;
    int pz = p / 144;
    int py = (p / 12) % 12;
    int px = p % 12;
    int i = e >> 6;                 // 0..7
    int j = (e >> 3) & 7;
    int k = e & 7;
    size_t src = (size_t)b * IMG * IMG * IMG
               + (size_t)(pz * PP + i) * IMG * IMG
               + (size_t)(py * PP + j) * IMG
               + (px * PP + k);
    g_patches[(size_t)r * PK + e] = x[src];
}

// ---------------- cls token + pos embed row 0 ----------------
__global__ void cls_init_kernel(const float* __restrict__ cls_token,
                                const float* __restrict__ pos_embed) {
    int gid = blockIdx.x * blockDim.x + threadIdx.x;
    if (gid >= BATCH * EMB) return;
    int b = gid / EMB;
    int e = gid - b * EMB;
    g_t[(size_t)b * NTOK * EMB + e] = cls_token[e] + pos_embed[e];
}

// ---------------- generic fp32 GEMM:  C[M,N] = A[M,K] * W[N,K]^T  ----------------
// EPI: 0 = bias store, 1 = bias + exact GELU, 2 = bias + residual add into C,
//      3 = patch embed: bias + pos_embed, scattered into token buffer
#define BM 64
#define BN 64
#define BK 16

template<int EPI>
__global__ void gemm_kernel(const float* __restrict__ A, const float* __restrict__ W,
                            const float* __restrict__ bias, float* __restrict__ C,
                            int M, int N, int K, const float* __restrict__ extra) {
    __shared__ float As[BK][BM];
    __shared__ float Ws[BK][BN];
    const int tid = threadIdx.x;           // 256 threads
    const int tx = tid & 15;
    const int ty = tid >> 4;
    const int bm = blockIdx.y * BM;
    const int bn = blockIdx.x * BN;

    float acc[4][4] = {};

    for (int k0 = 0; k0 < K; k0 += BK) {
        #pragma unroll
        for (int l = 0; l < 4; l++) {
            int idx = tid + l * 256;       // 0..1023
            int mn = idx >> 4;             // 0..63
            int kk = idx & 15;
            int row = bm + mn;
            As[kk][mn] = (row < M) ? A[(size_t)row * K + k0 + kk] : 0.f;
            Ws[kk][mn] = W[(size_t)(bn + mn) * K + k0 + kk];
        }
        __syncthreads();
        #pragma unroll
        for (int kk = 0; kk < BK; kk++) {
            float4 a = *reinterpret_cast<const float4*>(&As[kk][ty * 4]);
            float4 w = *reinterpret_cast<const float4*>(&Ws[kk][tx * 4]);
            float av[4] = {a.x, a.y, a.z, a.w};
            float wv[4] = {w.x, w.y, w.z, w.w};
            #pragma unroll
            for (int i = 0; i < 4; i++)
                #pragma unroll
                for (int j = 0; j < 4; j++)
                    acc[i][j] += av[i] * wv[j];
        }
        __syncthreads();
    }

    #pragma unroll
    for (int i = 0; i < 4; i++) {
        int row = bm + ty * 4 + i;
        if (row >= M) continue;
        #pragma unroll
        for (int j = 0; j < 4; j++) {
            int col = bn + tx * 4 + j;
            float v = acc[i][j] + bias[col];
            if (EPI == 0) {
                C[(size_t)row * N + col] = v;
            } else if (EPI == 1) {
                // exact GELU: 0.5*x*(1+erf(x/sqrt(2)))
                C[(size_t)row * N + col] = 0.5f * v * (1.0f + erff(v * 0.70710678118654752f));
            } else if (EPI == 2) {
                size_t o = (size_t)row * N + col;
                C[o] = C[o] + v;
            } else { // EPI == 3: patch embed -> token buffer + pos_embed
                int b = row / NPATCH;
                int p = row - b * NPATCH;
                size_t o = ((size_t)b * NTOK + 1 + p) * EMB + col;
                C[o] = v + extra[(size_t)(1 + p) * EMB + col];
            }
        }
    }
}

// ---------------- LayerNorm over last dim (EMB) ----------------
__global__ void ln_kernel(const float* __restrict__ x, const float* __restrict__ w,
                          const float* __restrict__ bvec, float* __restrict__ y) {
    const int row = blockIdx.x;
    const float* xr = x + (size_t)row * EMB;
    const int tid = threadIdx.x;           // 128
    float s = 0.f, s2 = 0.f;
    #pragma unroll
    for (int e = tid; e < EMB; e += 128) {
        float v = xr[e];
        s += v; s2 += v * v;
    }
    #pragma unroll
    for (int o = 16; o; o >>= 1) {
        s  += __shfl_xor_sync(0xffffffffu, s,  o);
        s2 += __shfl_xor_sync(0xffffffffu, s2, o);
    }
    __shared__ float r1[4], r2[4];
    if ((tid & 31) == 0) { r1[tid >> 5] = s; r2[tid >> 5] = s2; }
    __syncthreads();
    float S  = r1[0] + r1[1] + r1[2] + r1[3];
    float S2 = r2[0] + r2[1] + r2[2] + r2[3];
    float mu = S * (1.0f / EMB);
    float var = S2 * (1.0f / EMB) - mu * mu;
    float rs = rsqrtf(var + 1e-5f);
    float* yr = y + (size_t)row * EMB;
    #pragma unroll
    for (int e = tid; e < EMB; e += 128)
        yr[e] = (xr[e] - mu) * rs * w[e] + bvec[e];
}

// ---------------- attention: one block per (b, h, query n) ----------------
#define ATT_T 128
__global__ void attn_kernel(const float* __restrict__ qkv, float* __restrict__ out) {
    const int n = blockIdx.x;
    const int h = blockIdx.y;
    const int b = blockIdx.z;
    __shared__ float sq[HD];
    __shared__ float ss[NTOK];
    __shared__ float sred[4];
    __shared__ float vred[4][HD];
    const int tid = threadIdx.x;

    const float* qp = qkv + ((size_t)(b * NTOK + n)) * QKVD + h * HD;
    if (tid < HD) sq[tid] = qp[tid];
    __syncthreads();

    const float scale = rsqrtf((float)HD);
    float lmax = -1e30f;
    for (int m = tid; m < NTOK; m += ATT_T) {
        const float* kp = qkv + ((size_t)(b * NTOK + m)) * QKVD + EMB + h * HD;
        float s = 0.f;
        #pragma unroll
        for (int d = 0; d < HD; d++) s += sq[d] * kp[d];
        s *= scale;
        ss[m] = s;
        lmax = fmaxf(lmax, s);
    }
    #pragma unroll
    for (int o = 16; o; o >>= 1) lmax = fmaxf(lmax, __shfl_xor_sync(0xffffffffu, lmax, o));
    if ((tid & 31) == 0) sred[tid >> 5] = lmax;
    __syncthreads();
    float gmax = fmaxf(fmaxf(sred[0], sred[1]), fmaxf(sred[2], sred[3]));
    __syncthreads();

    float lsum = 0.f;
    float acc[HD];
    #pragma unroll
    for (int d = 0; d < HD; d++) acc[d] = 0.f;
    for (int m = tid; m < NTOK; m += ATT_T) {
        float p = expf(ss[m] - gmax);
        lsum += p;
        const float* vp = qkv + ((size_t)(b * NTOK + m)) * QKVD + 2 * EMB + h * HD;
        #pragma unroll
        for (int d = 0; d < HD; d++) acc[d] += p * vp[d];
    }
    #pragma unroll
    for (int o = 16; o; o >>= 1) lsum += __shfl_xor_sync(0xffffffffu, lsum, o);
    if ((tid & 31) == 0) sred[tid >> 5] = lsum;
    #pragma unroll
    for (int d = 0; d < HD; d++)
        #pragma unroll
        for (int o = 16; o; o >>= 1) acc[d] += __shfl_xor_sync(0xffffffffu, acc[d], o);
    if ((tid & 31) == 0) {
        #pragma unroll
        for (int d = 0; d < HD; d++) vred[tid >> 5][d] = acc[d];
    }
    __syncthreads();
    if (tid < HD) {
        float gsum = sred[0] + sred[1] + sred[2] + sred[3];
        float r = (vred[0][tid] + vred[1][tid] + vred[2][tid] + vred[3][tid]) / gsum;
        out[((size_t)(b * NTOK + n)) * EMB + h * HD + tid] = r;
    }
}

// ---------------- final LN(row 0) + classification head ----------------
__global__ void head_kernel(const float* __restrict__ t, const float* __restrict__ nw,
                            const float* __restrict__ nb, const float* __restrict__ hw,
                            const float* __restrict__ hb, float* __restrict__ out) {
    const int b = blockIdx.x;
    const float* xr = t + (size_t)b * NTOK * EMB;   // token 0
    const int tid = threadIdx.x;                     // 128
    float s = 0.f, s2 = 0.f;
    for (int e = tid; e < EMB; e += 128) { float v = xr[e]; s += v; s2 += v * v; }
    #pragma unroll
    for (int o = 16; o; o >>= 1) {
        s  += __shfl_xor_sync(0xffffffffu, s,  o);
        s2 += __shfl_xor_sync(0xffffffffu, s2, o);
    }
    __shared__ float r1[4], r2[4], rd0[4], rd1[4];
    if ((tid & 31) == 0) { r1[tid >> 5] = s; r2[tid >> 5] = s2; }
    __syncthreads();
    float S  = r1[0] + r1[1] + r1[2] + r1[3];
    float S2 = r2[0] + r2[1] + r2[2] + r2[3];
    float mu = S * (1.0f / EMB);
    float rs = rsqrtf(S2 * (1.0f / EMB) - mu * mu + 1e-5f);
    float d0 = 0.f, d1 = 0.f;
    for (int e = tid; e < EMB; e += 128) {
        float nv = (xr[e] - mu) * rs * nw[e] + nb[e];
        d0 += nv * hw[e];
        d1 += nv * hw[EMB + e];
    }
    #pragma unroll
    for (int o = 16; o; o >>= 1) {
        d0 += __shfl_xor_sync(0xffffffffu, d0, o);
        d1 += __shfl_xor_sync(0xffffffffu, d1, o);
    }
    if ((tid & 31) == 0) { rd0[tid >> 5] = d0; rd1[tid >> 5] = d1; }
    __syncthreads();
    if (tid == 0) {
        out[b * NC + 0] = rd0[0] + rd0[1] + rd0[2] + rd0[3] + hb[0];
        out[b * NC + 1] = rd1[0] + rd1[1] + rd1[2] + rd1[3] + hb[1];
    }
}

// ---------------- host orchestration ----------------
extern "C" void kernel_launch(void* const* d_in, const int* in_sizes, int n_in,
                              void* d_out, int out_size) {
    const float* x         = (const float*)d_in[0];
    const float* conv_w    = (const float*)d_in[1];
    const float* conv_b    = (const float*)d_in[2];
    const float* cls_token = (const float*)d_in[3];
    const float* pos_embed = (const float*)d_in[4];
    const float* ln1_w     = (const float*)d_in[5];
    const float* ln1_b     = (const float*)d_in[6];
    const float* qkv_w     = (const float*)d_in[7];
    const float* qkv_b     = (const float*)d_in[8];
    const float* proj_w    = (const float*)d_in[9];
    const float* proj_b    = (const float*)d_in[10];
    const float* ln2_w     = (const float*)d_in[11];
    const float* ln2_b     = (const float*)d_in[12];
    const float* mlp_w1    = (const float*)d_in[13];
    const float* mlp_b1    = (const float*)d_in[14];
    const float* mlp_w2    = (const float*)d_in[15];
    const float* mlp_b2    = (const float*)d_in[16];
    const float* norm_w    = (const float*)d_in[17];
    const float* norm_b    = (const float*)d_in[18];
    const float* head_w    = (const float*)d_in[19];
    const float* head_b    = (const float*)d_in[20];
    float* out = (float*)d_out;

    float *patches, *t, *h, *qkv, *attno, *mlp;
    cudaGetSymbolAddress((void**)&patches, g_patches);
    cudaGetSymbolAddress((void**)&t,       g_t);
    cudaGetSymbolAddress((void**)&h,       g_h);
    cudaGetSymbolAddress((void**)&qkv,     g_qkv);
    cudaGetSymbolAddress((void**)&attno,   g_attno);
    cudaGetSymbolAddress((void**)&mlp,     g_mlp);

    const int Mtok = BATCH * NTOK;   // 3458
    const int Mpat = BATCH * NPATCH; // 3456

    // 1) patchify + patch-embed GEMM (scatter into token buffer with pos_embed)
    {
        int total = BATCH * NPATCH * PK;
        patchify_kernel<<<(total + 255) / 256, 256>>>(x);
        dim3 grid(EMB / BN, (Mpat + BM - 1) / BM);
        gemm_kernel<3><<<grid, 256>>>(patches, conv_w, conv_b, t, Mpat, EMB, PK, pos_embed);
        cls_init_kernel<<<(BATCH * EMB + 255) / 256, 256>>>(cls_token, pos_embed);
    }

    // 2) transformer layers
    for (int i = 0; i < NL; i++) {
        // LN1 -> h
        ln_kernel<<<Mtok, 128>>>(t, ln1_w + i * EMB, ln1_b + i * EMB, h);
        // qkv = h @ qkv_w^T + b
        {
            dim3 grid(QKVD / BN, (Mtok + BM - 1) / BM);
            gemm_kernel<0><<<grid, 256>>>(h, qkv_w + (size_t)i * QKVD * EMB,
                                          qkv_b + i * QKVD, qkv, Mtok, QKVD, EMB, nullptr);
        }
        // attention -> attno
        {
            dim3 grid(NTOK, NH, BATCH);
            attn_kernel<<<grid, ATT_T>>>(qkv, attno);
        }
        // t += attno @ proj_w^T + b
        {
            dim3 grid(EMB / BN, (Mtok + BM - 1) / BM);
            gemm_kernel<2><<<grid, 256>>>(attno, proj_w + (size_t)i * EMB * EMB,
                                          proj_b + i * EMB, t, Mtok, EMB, EMB, nullptr);
        }
        // LN2 -> h
        ln_kernel<<<Mtok, 128>>>(t, ln2_w + i * EMB, ln2_b + i * EMB, h);
        // mlp = gelu(h @ w1^T + b1)
        {
            dim3 grid(MLPD / BN, (Mtok + BM - 1) / BM);
            gemm_kernel<1><<<grid, 256>>>(h, mlp_w1 + (size_t)i * MLPD * EMB,
                                          mlp_b1 + i * MLPD, mlp, Mtok, MLPD, EMB, nullptr);
        }
        // t += mlp @ w2^T + b2
        {
            dim3 grid(EMB / BN, (Mtok + BM - 1) / BM);
            gemm_kernel<2><<<grid, 256>>>(mlp, mlp_w2 + (size_t)i * EMB * MLPD,
                                          mlp_b2 + i * EMB, t, Mtok, EMB, MLPD, nullptr);
        }
    }

    // 3) final LN on cls token + head
    head_kernel<<<BATCH, 128>>>(t, norm_w, norm_b, head_w, head_b, out);
}

// round 10
// speedup vs baseline: 13.9985x; 13.9937x over previous
#include <cuda_runtime.h>
#include <cuda_bf16.h>
#include <math.h>

// ---------------- problem constants ----------------
#define BATCH   2
#define IMG     96
#define PP      8
#define EMB     384
#define NH      8
#define HD      48
#define NL      6
#define MLPD    1536
#define NC      2
#define NPATCH  1728            // (96/8)^3
#define NTOK    1729            // NPATCH + 1
#define PK      512             // P^3 * CIN
#define QKVD    1152            // 3*EMB

// ---------------- device scratch (static, allocation-free) ----------------
__device__ float g_patches[BATCH * NPATCH * PK];
__device__ float g_t     [BATCH * NTOK * EMB];
__device__ float g_h     [BATCH * NTOK * EMB];
__device__ float g_qkv   [BATCH * NTOK * QKVD];
__device__ float g_attno [BATCH * NTOK * EMB];
__device__ float g_mlp   [BATCH * NTOK * MLPD];

// ---------------- small helpers ----------------
__device__ __forceinline__ unsigned f2tf32(float f) {
    unsigned r;
    asm("cvt.rna.tf32.f32 %0, %1;" : "=r"(r) : "f"(f));
    return r;
}

__device__ __forceinline__ void mma_tf32(float c[4], const unsigned a[4],
                                         unsigned b0, unsigned b1) {
    asm volatile(
        "mma.sync.aligned.m16n8k8.row.col.f32.tf32.tf32.f32 "
        "{%0,%1,%2,%3}, {%4,%5,%6,%7}, {%8,%9}, {%0,%1,%2,%3};"
        : "+f"(c[0]), "+f"(c[1]), "+f"(c[2]), "+f"(c[3])
        : "r"(a[0]), "r"(a[1]), "r"(a[2]), "r"(a[3]), "r"(b0), "r"(b1));
}

// ---------------- patchify ----------------
__global__ void patchify_kernel(const float* __restrict__ x) {
    int gid = blockIdx.x * blockDim.x + threadIdx.x;
    const int total = BATCH * NPATCH * PK;
    if (gid >= total) return;
    int e = gid & (PK - 1);
    int r = gid >> 9;
    int b = r / NPATCH;
    int p = r - b * NPATCH;
    int pz = p / 144;
    int py = (p / 12) % 12;
    int px = p % 12;
    int i = e >> 6;
    int j = (e >> 3) & 7;
    int k = e & 7;
    size_t src = (size_t)b * IMG * IMG * IMG
               + (size_t)(pz * PP + i) * IMG * IMG
               + (size_t)(py * PP + j) * IMG
               + (px * PP + k);
    g_patches[(size_t)r * PK + e] = x[src];
}

__global__ void cls_init_kernel(const float* __restrict__ cls_token,
                                const float* __restrict__ pos_embed) {
    int gid = blockIdx.x * blockDim.x + threadIdx.x;
    if (gid >= BATCH * EMB) return;
    int b = gid / EMB;
    int e = gid - b * EMB;
    g_t[(size_t)b * NTOK * EMB + e] = cls_token[e] + pos_embed[e];
}

// ---------------- 3xTF32 tensor-core GEMM: C[M,N] = A[M,K] * W[N,K]^T ----------------
// Precision: a = a_hi + a_lo (tf32 split), C += ah*bh + ah*bl + al*bh  (~fp32)
// EPI: 0 = bias, 1 = bias+GELU, 2 = bias+residual add, 3 = patch scatter + pos_embed
#define GBM 128
#define GBN 128
#define GBK 16
#define GSTR 20      // 16 + 4 pad (conflict-free fragment loads)

template<int EPI>
__global__ void __launch_bounds__(256, 1)
gemm_tc(const float* __restrict__ A, const float* __restrict__ W,
        const float* __restrict__ bias, float* __restrict__ C,
        int M, int N, int K, const float* __restrict__ extra)
{
    __shared__ unsigned AsH[GBM * GSTR];
    __shared__ unsigned AsL[GBM * GSTR];
    __shared__ unsigned BsH[GBN * GSTR];
    __shared__ unsigned BsL[GBN * GSTR];

    const int tid  = threadIdx.x;
    const int lane = tid & 31;
    const int warp = tid >> 5;
    const int wm = (warp & 3) * 32;    // warp row offset
    const int wn = (warp >> 2) * 64;   // warp col offset
    const int bm = blockIdx.y * GBM;
    const int bn = blockIdx.x * GBN;
    const int g  = lane >> 2;          // 0..7
    const int tg = lane & 3;           // 0..3

    // global->smem load mapping: 512 float4 per matrix per k-tile, 2 per thread
    const int r0 = tid >> 2;           // 0..63
    const int r1 = r0 + 64;            // 64..127
    const int c4 = (tid & 3) * 4;      // k offset 0,4,8,12

    float c[2][8][4];
    #pragma unroll
    for (int i = 0; i < 2; i++)
        #pragma unroll
        for (int j = 0; j < 8; j++)
            #pragma unroll
            for (int v = 0; v < 4; v++) c[i][j][v] = 0.f;

    const float4 z4 = make_float4(0.f, 0.f, 0.f, 0.f);
    float4 av0, av1, wv0, wv1;

    // prologue: fetch k-tile 0 into registers
    av0 = (bm + r0 < M) ? *(const float4*)&A[(size_t)(bm + r0) * K + c4] : z4;
    av1 = (bm + r1 < M) ? *(const float4*)&A[(size_t)(bm + r1) * K + c4] : z4;
    wv0 = *(const float4*)&W[(size_t)(bn + r0) * K + c4];
    wv1 = *(const float4*)&W[(size_t)(bn + r1) * K + c4];

    const int nIter = K >> 4;
    for (int it = 0; it < nIter; it++) {
        // ---- registers -> smem (hi/lo split) ----
        {
            float v[4];
            v[0]=av0.x; v[1]=av0.y; v[2]=av0.z; v[3]=av0.w;
            #pragma unroll
            for (int u = 0; u < 4; u++) {
                unsigned hi = f2tf32(v[u]);
                AsH[r0 * GSTR + c4 + u] = hi;
                AsL[r0 * GSTR + c4 + u] = f2tf32(v[u] - __uint_as_float(hi));
            }
            v[0]=av1.x; v[1]=av1.y; v[2]=av1.z; v[3]=av1.w;
            #pragma unroll
            for (int u = 0; u < 4; u++) {
                unsigned hi = f2tf32(v[u]);
                AsH[r1 * GSTR + c4 + u] = hi;
                AsL[r1 * GSTR + c4 + u] = f2tf32(v[u] - __uint_as_float(hi));
            }
            v[0]=wv0.x; v[1]=wv0.y; v[2]=wv0.z; v[3]=wv0.w;
            #pragma unroll
            for (int u = 0; u < 4; u++) {
                unsigned hi = f2tf32(v[u]);
                BsH[r0 * GSTR + c4 + u] = hi;
                BsL[r0 * GSTR + c4 + u] = f2tf32(v[u] - __uint_as_float(hi));
            }
            v[0]=wv1.x; v[1]=wv1.y; v[2]=wv1.z; v[3]=wv1.w;
            #pragma unroll
            for (int u = 0; u < 4; u++) {
                unsigned hi = f2tf32(v[u]);
                BsH[r1 * GSTR + c4 + u] = hi;
                BsL[r1 * GSTR + c4 + u] = f2tf32(v[u] - __uint_as_float(hi));
            }
        }
        __syncthreads();

        // ---- prefetch next k-tile globals (overlaps with MMA below) ----
        if (it + 1 < nIter) {
            int k0 = (it + 1) << 4;
            av0 = (bm + r0 < M) ? *(const float4*)&A[(size_t)(bm + r0) * K + k0 + c4] : z4;
            av1 = (bm + r1 < M) ? *(const float4*)&A[(size_t)(bm + r1) * K + k0 + c4] : z4;
            wv0 = *(const float4*)&W[(size_t)(bn + r0) * K + k0 + c4];
            wv1 = *(const float4*)&W[(size_t)(bn + r1) * K + k0 + c4];
        }

        // ---- compute ----
        #pragma unroll
        for (int ks = 0; ks < 2; ks++) {
            const int kb = ks * 8 + tg;
            unsigned afH[2][4], afL[2][4];
            #pragma unroll
            for (int i = 0; i < 2; i++) {
                int row = wm + i * 16 + g;
                afH[i][0] = AsH[row * GSTR + kb];
                afH[i][1] = AsH[(row + 8) * GSTR + kb];
                afH[i][2] = AsH[row * GSTR + kb + 4];
                afH[i][3] = AsH[(row + 8) * GSTR + kb + 4];
                afL[i][0] = AsL[row * GSTR + kb];
                afL[i][1] = AsL[(row + 8) * GSTR + kb];
                afL[i][2] = AsL[row * GSTR + kb + 4];
                afL[i][3] = AsL[(row + 8) * GSTR + kb + 4];
            }
            #pragma unroll
            for (int j = 0; j < 8; j++) {
                int col = wn + j * 8 + g;
                unsigned bh0 = BsH[col * GSTR + kb];
                unsigned bh1 = BsH[col * GSTR + kb + 4];
                unsigned bl0 = BsL[col * GSTR + kb];
                unsigned bl1 = BsL[col * GSTR + kb + 4];
                #pragma unroll
                for (int i = 0; i < 2; i++) {
                    mma_tf32(c[i][j], afH[i], bh0, bh1);   // hi*hi
                    mma_tf32(c[i][j], afH[i], bl0, bl1);   // hi*lo
                    mma_tf32(c[i][j], afL[i], bh0, bh1);   // lo*hi
                }
            }
        }
        __syncthreads();
    }

    // ---- epilogue ----
    #pragma unroll
    for (int i = 0; i < 2; i++) {
        #pragma unroll
        for (int half = 0; half < 2; half++) {
            int r = bm + wm + i * 16 + g + half * 8;
            if (r >= M) continue;
            #pragma unroll
            for (int j = 0; j < 8; j++) {
                int col = bn + wn + j * 8 + tg * 2;
                float v0 = c[i][j][half * 2 + 0] + bias[col];
                float v1 = c[i][j][half * 2 + 1] + bias[col + 1];
                if (EPI == 0) {
                    C[(size_t)r * N + col]     = v0;
                    C[(size_t)r * N + col + 1] = v1;
                } else if (EPI == 1) {
                    C[(size_t)r * N + col]     = 0.5f * v0 * (1.0f + erff(v0 * 0.70710678118654752f));
                    C[(size_t)r * N + col + 1] = 0.5f * v1 * (1.0f + erff(v1 * 0.70710678118654752f));
                } else if (EPI == 2) {
                    size_t o = (size_t)r * N + col;
                    C[o]     += v0;
                    C[o + 1] += v1;
                } else { // patch scatter
                    int b = r / NPATCH;
                    int p = r - b * NPATCH;
                    size_t o = ((size_t)b * NTOK + 1 + p) * EMB + col;
                    C[o]     = v0 + extra[(size_t)(1 + p) * EMB + col];
                    C[o + 1] = v1 + extra[(size_t)(1 + p) * EMB + col + 1];
                }
            }
        }
    }
}

// ---------------- LayerNorm ----------------
__global__ void ln_kernel(const float* __restrict__ x, const float* __restrict__ w,
                          const float* __restrict__ bvec, float* __restrict__ y) {
    const int row = blockIdx.x;
    const float* xr = x + (size_t)row * EMB;
    const int tid = threadIdx.x;           // 128
    float s = 0.f, s2 = 0.f;
    #pragma unroll
    for (int e = tid; e < EMB; e += 128) {
        float v = xr[e];
        s += v; s2 += v * v;
    }
    #pragma unroll
    for (int o = 16; o; o >>= 1) {
        s  += __shfl_xor_sync(0xffffffffu, s,  o);
        s2 += __shfl_xor_sync(0xffffffffu, s2, o);
    }
    __shared__ float r1[4], r2[4];
    if ((tid & 31) == 0) { r1[tid >> 5] = s; r2[tid >> 5] = s2; }
    __syncthreads();
    float S  = r1[0] + r1[1] + r1[2] + r1[3];
    float S2 = r2[0] + r2[1] + r2[2] + r2[3];
    float mu = S * (1.0f / EMB);
    float var = S2 * (1.0f / EMB) - mu * mu;
    float rs = rsqrtf(var + 1e-5f);
    float* yr = y + (size_t)row * EMB;
    #pragma unroll
    for (int e = tid; e < EMB; e += 128)
        yr[e] = (xr[e] - mu) * rs * w[e] + bvec[e];
}

// ---------------- flash attention: block = (64 queries, one (b,h)) ----------------
#define QT 64
#define KT 48
#define AST 52     // padded row stride (floats): 16B-aligned, conflict-free

__global__ void __launch_bounds__(256, 1)
attn_flash(const float* __restrict__ qkv, float* __restrict__ out) {
    __shared__ float Qs[QT * AST];
    __shared__ float Ks[KT * AST];
    __shared__ float Vs[KT * AST];
    __shared__ float Ps[QT * AST];

    const int tid = threadIdx.x;
    const int h = blockIdx.y, b = blockIdx.z;
    const int qbase = blockIdx.x * QT;
    const int q   = tid >> 2;     // 0..63 query within tile
    const int sub = tid & 3;      // quad lane

    // ---- load Q tile (64 x 48), coalesced float4 ----
    #pragma unroll
    for (int l = 0; l < 3; l++) {
        int idx = tid + 256 * l;          // 0..767
        int row = idx / 12, cc = idx % 12;
        int gq = qbase + row;
        float4 v = (gq < NTOK)
            ? *(const float4*)&qkv[((size_t)(b * NTOK + gq)) * QKVD + h * HD + cc * 4]
            : make_float4(0.f, 0.f, 0.f, 0.f);
        *(float4*)&Qs[row * AST + cc * 4] = v;
    }

    const float scale = 0.14433756729740643f;  // 1/sqrt(48)
    float m = -1e30f, l_sum = 0.f;
    float acc[12];
    #pragma unroll
    for (int j = 0; j < 12; j++) acc[j] = 0.f;

    const int ntiles = (NTOK + KT - 1) / KT;   // 37
    for (int t0 = 0; t0 < ntiles; t0++) {
        const int kbase = t0 * KT;
        __syncthreads();   // protect Ks/Vs/Ps from prior-iteration readers
        // ---- load K,V tiles (48 x 48 each), coalesced ----
        #pragma unroll
        for (int l = 0; l < 3; l++) {
            int idx = tid + 256 * l;
            if (idx < KT * 12) {
                int row = idx / 12, cc = idx % 12;
                int gk = kbase + row;
                float4 kv, vv;
                if (gk < NTOK) {
                    size_t base = ((size_t)(b * NTOK + gk)) * QKVD + h * HD;
                    kv = *(const float4*)&qkv[base + EMB + cc * 4];
                    vv = *(const float4*)&qkv[base + 2 * EMB + cc * 4];
                } else {
                    kv = make_float4(0.f, 0.f, 0.f, 0.f);
                    vv = kv;
                }
                *(float4*)&Ks[row * AST + cc * 4] = kv;
                *(float4*)&Vs[row * AST + cc * 4] = vv;
            }
        }
        __syncthreads();

        // ---- scores: this thread handles 12 keys k = sub + 4*kk ----
        float s[12];
        #pragma unroll
        for (int kk = 0; kk < 12; kk++) s[kk] = 0.f;
        #pragma unroll
        for (int d4 = 0; d4 < 12; d4++) {
            float4 qd = *(const float4*)&Qs[q * AST + d4 * 4];
            #pragma unroll
            for (int kk = 0; kk < 12; kk++) {
                int k = sub + 4 * kk;
                float4 kd = *(const float4*)&Ks[k * AST + d4 * 4];
                s[kk] += qd.x * kd.x + qd.y * kd.y + qd.z * kd.z + qd.w * kd.w;
            }
        }
        float tmax = -1e30f;
        #pragma unroll
        for (int kk = 0; kk < 12; kk++) {
            int k = sub + 4 * kk;
            s[kk] = (kbase + k < NTOK) ? s[kk] * scale : -1e30f;
            tmax = fmaxf(tmax, s[kk]);
        }
        tmax = fmaxf(tmax, __shfl_xor_sync(0xffffffffu, tmax, 1));
        tmax = fmaxf(tmax, __shfl_xor_sync(0xffffffffu, tmax, 2));
        float mnew = fmaxf(m, tmax);
        float alpha = __expf(m - mnew);
        float psum = 0.f;
        #pragma unroll
        for (int kk = 0; kk < 12; kk++) {
            float p = __expf(s[kk] - mnew);
            psum += p;
            Ps[q * AST + sub + 4 * kk] = p;
        }
        psum += __shfl_xor_sync(0xffffffffu, psum, 1);
        psum += __shfl_xor_sync(0xffffffffu, psum, 2);
        l_sum = l_sum * alpha + psum;
        m = mnew;
        #pragma unroll
        for (int j = 0; j < 12; j++) acc[j] *= alpha;
        __syncthreads();   // Ps visible to all quad members

        // ---- P @ V : this thread owns dims d0..d0+11 of query q ----
        const int d0 = sub * 12;
        #pragma unroll 4
        for (int k = 0; k < KT; k++) {
            float p = Ps[q * AST + k];
            float4 v0 = *(const float4*)&Vs[k * AST + d0];
            float4 v1 = *(const float4*)&Vs[k * AST + d0 + 4];
            float4 v2 = *(const float4*)&Vs[k * AST + d0 + 8];
            acc[0] += p * v0.x; acc[1] += p * v0.y; acc[2]  += p * v0.z; acc[3]  += p * v0.w;
            acc[4] += p * v1.x; acc[5] += p * v1.y; acc[6]  += p * v1.z; acc[7]  += p * v1.w;
            acc[8] += p * v2.x; acc[9] += p * v2.y; acc[10] += p * v2.z; acc[11] += p * v2.w;
        }
    }

    int gq = qbase + q;
    if (gq < NTOK) {
        float inv = 1.0f / l_sum;
        size_t o = ((size_t)(b * NTOK + gq)) * EMB + h * HD + sub * 12;
        #pragma unroll
        for (int j = 0; j < 12; j++) out[o + j] = acc[j] * inv;
    }
}

// ---------------- final LN(cls) + head ----------------
__global__ void head_kernel(const float* __restrict__ t, const float* __restrict__ nw,
                            const float* __restrict__ nb, const float* __restrict__ hw,
                            const float* __restrict__ hb, float* __restrict__ out) {
    const int b = blockIdx.x;
    const float* xr = t + (size_t)b * NTOK * EMB;
    const int tid = threadIdx.x;
    float s = 0.f, s2 = 0.f;
    for (int e = tid; e < EMB; e += 128) { float v = xr[e]; s += v; s2 += v * v; }
    #pragma unroll
    for (int o = 16; o; o >>= 1) {
        s  += __shfl_xor_sync(0xffffffffu, s,  o);
        s2 += __shfl_xor_sync(0xffffffffu, s2, o);
    }
    __shared__ float r1[4], r2[4], rd0[4], rd1[4];
    if ((tid & 31) == 0) { r1[tid >> 5] = s; r2[tid >> 5] = s2; }
    __syncthreads();
    float S  = r1[0] + r1[1] + r1[2] + r1[3];
    float S2 = r2[0] + r2[1] + r2[2] + r2[3];
    float mu = S * (1.0f / EMB);
    float rs = rsqrtf(S2 * (1.0f / EMB) - mu * mu + 1e-5f);
    float d0 = 0.f, d1 = 0.f;
    for (int e = tid; e < EMB; e += 128) {
        float nv = (xr[e] - mu) * rs * nw[e] + nb[e];
        d0 += nv * hw[e];
        d1 += nv * hw[EMB + e];
    }
    #pragma unroll
    for (int o = 16; o; o >>= 1) {
        d0 += __shfl_xor_sync(0xffffffffu, d0, o);
        d1 += __shfl_xor_sync(0xffffffffu, d1, o);
    }
    if ((tid & 31) == 0) { rd0[tid >> 5] = d0; rd1[tid >> 5] = d1; }
    __syncthreads();
    if (tid == 0) {
        out[b * NC + 0] = rd0[0] + rd0[1] + rd0[2] + rd0[3] + hb[0];
        out[b * NC + 1] = rd1[0] + rd1[1] + rd1[2] + rd1[3] + hb[1];
    }
}

// ---------------- host orchestration ----------------
extern "C" void kernel_launch(void* const* d_in, const int* in_sizes, int n_in,
                              void* d_out, int out_size) {
    const float* x         = (const float*)d_in[0];
    const float* conv_w    = (const float*)d_in[1];
    const float* conv_b    = (const float*)d_in[2];
    const float* cls_token = (const float*)d_in[3];
    const float* pos_embed = (const float*)d_in[4];
    const float* ln1_w     = (const float*)d_in[5];
    const float* ln1_b     = (const float*)d_in[6];
    const float* qkv_w     = (const float*)d_in[7];
    const float* qkv_b     = (const float*)d_in[8];
    const float* proj_w    = (const float*)d_in[9];
    const float* proj_b    = (const float*)d_in[10];
    const float* ln2_w     = (const float*)d_in[11];
    const float* ln2_b     = (const float*)d_in[12];
    const float* mlp_w1    = (const float*)d_in[13];
    const float* mlp_b1    = (const float*)d_in[14];
    const float* mlp_w2    = (const float*)d_in[15];
    const float* mlp_b2    = (const float*)d_in[16];
    const float* norm_w    = (const float*)d_in[17];
    const float* norm_b    = (const float*)d_in[18];
    const float* head_w    = (const float*)d_in[19];
    const float* head_b    = (const float*)d_in[20];
    float* out = (float*)d_out;

    float *patches, *t, *h, *qkv, *attno, *mlp;
    cudaGetSymbolAddress((void**)&patches, g_patches);
    cudaGetSymbolAddress((void**)&t,       g_t);
    cudaGetSymbolAddress((void**)&h,       g_h);
    cudaGetSymbolAddress((void**)&qkv,     g_qkv);
    cudaGetSymbolAddress((void**)&attno,   g_attno);
    cudaGetSymbolAddress((void**)&mlp,     g_mlp);

    const int Mtok = BATCH * NTOK;   // 3458
    const int Mpat = BATCH * NPATCH; // 3456
    const int MtokBlocks = (Mtok + GBM - 1) / GBM;  // 28

    // 1) patchify + patch-embed GEMM + cls
    {
        int total = BATCH * NPATCH * PK;
        patchify_kernel<<<(total + 255) / 256, 256>>>(x);
        dim3 grid(EMB / GBN, Mpat / GBM);
        gemm_tc<3><<<grid, 256>>>(patches, conv_w, conv_b, t, Mpat, EMB, PK, pos_embed);
        cls_init_kernel<<<(BATCH * EMB + 255) / 256, 256>>>(cls_token, pos_embed);
    }

    // 2) transformer layers
    for (int i = 0; i < NL; i++) {
        ln_kernel<<<Mtok, 128>>>(t, ln1_w + i * EMB, ln1_b + i * EMB, h);
        {
            dim3 grid(QKVD / GBN, MtokBlocks);
            gemm_tc<0><<<grid, 256>>>(h, qkv_w + (size_t)i * QKVD * EMB,
                                      qkv_b + i * QKVD, qkv, Mtok, QKVD, EMB, nullptr);
        }
        {
            dim3 grid((NTOK + QT - 1) / QT, NH, BATCH);
            attn_flash<<<grid, 256>>>(qkv, attno);
        }
        {
            dim3 grid(EMB / GBN, MtokBlocks);
            gemm_tc<2><<<grid, 256>>>(attno, proj_w + (size_t)i * EMB * EMB,
                                      proj_b + i * EMB, t, Mtok, EMB, EMB, nullptr);
        }
        ln_kernel<<<Mtok, 128>>>(t, ln2_w + i * EMB, ln2_b + i * EMB, h);
        {
            dim3 grid(MLPD / GBN, MtokBlocks);
            gemm_tc<1><<<grid, 256>>>(h, mlp_w1 + (size_t)i * MLPD * EMB,
                                      mlp_b1 + i * MLPD, mlp, Mtok, MLPD, EMB, nullptr);
        }
        {
            dim3 grid(EMB / GBN, MtokBlocks);
            gemm_tc<2><<<grid, 256>>>(mlp, mlp_w2 + (size_t)i * EMB * MLPD,
                                      mlp_b2 + i * EMB, t, Mtok, EMB, MLPD, nullptr);
        }
    }

    // 3) head
    head_kernel<<<BATCH, 128>>>(t, norm_w, norm_b, head_w, head_b, out);
}

// round 11
// speedup vs baseline: 17.2390x; 1.2315x over previous
#include <cuda_runtime.h>
#include <cuda_bf16.h>
#include <math.h>

// ---------------- problem constants ----------------
#define BATCH   2
#define IMG     96
#define PP      8
#define EMB     384
#define NH      8
#define HD      48
#define NL      6
#define MLPD    1536
#define NC      2
#define NPATCH  1728            // (96/8)^3
#define NTOK    1729            // NPATCH + 1
#define PK      512             // P^3 * CIN
#define QKVD    1152            // 3*EMB

// ---------------- device scratch (static, allocation-free) ----------------
__device__ float g_patches[BATCH * NPATCH * PK];
__device__ float g_t     [BATCH * NTOK * EMB];
__device__ float g_h     [BATCH * NTOK * EMB];
__device__ float g_qkv   [BATCH * NTOK * QKVD];
__device__ float g_attno [BATCH * NTOK * EMB];
__device__ float g_mlp   [BATCH * NTOK * MLPD];

// ---------------- small helpers ----------------
// split fp32 pair into packed bf16x2 hi and lo words (hi+lo ~ 16-17 mantissa bits)
__device__ __forceinline__ void split_pair(float x, float y, unsigned &hi, unsigned &lo) {
    __nv_bfloat16 hx = __float2bfloat16(x);
    __nv_bfloat16 hy = __float2bfloat16(y);
    hi = ((unsigned)__bfloat16_as_ushort(hy) << 16) | (unsigned)__bfloat16_as_ushort(hx);
    float rx = x - __bfloat162float(hx);
    float ry = y - __bfloat162float(hy);
    __nv_bfloat16 lx = __float2bfloat16(rx);
    __nv_bfloat16 ly = __float2bfloat16(ry);
    lo = ((unsigned)__bfloat16_as_ushort(ly) << 16) | (unsigned)__bfloat16_as_ushort(lx);
}

__device__ __forceinline__ void mma_bf16(float c[4], const unsigned a[4],
                                         unsigned b0, unsigned b1) {
    asm volatile(
        "mma.sync.aligned.m16n8k16.row.col.f32.bf16.bf16.f32 "
        "{%0,%1,%2,%3}, {%4,%5,%6,%7}, {%8,%9}, {%0,%1,%2,%3};"
        : "+f"(c[0]), "+f"(c[1]), "+f"(c[2]), "+f"(c[3])
        : "r"(a[0]), "r"(a[1]), "r"(a[2]), "r"(a[3]), "r"(b0), "r"(b1));
}

// ---------------- patchify ----------------
__global__ void patchify_kernel(const float* __restrict__ x) {
    int gid = blockIdx.x * blockDim.x + threadIdx.x;
    const int total = BATCH * NPATCH * PK;
    if (gid >= total) return;
    int e = gid & (PK - 1);
    int r = gid >> 9;
    int b = r / NPATCH;
    int p = r - b * NPATCH;
    int pz = p / 144;
    int py = (p / 12) % 12;
    int px = p % 12;
    int i = e >> 6;
    int j = (e >> 3) & 7;
    int k = e & 7;
    size_t src = (size_t)b * IMG * IMG * IMG
               + (size_t)(pz * PP + i) * IMG * IMG
               + (size_t)(py * PP + j) * IMG
               + (px * PP + k);
    g_patches[(size_t)r * PK + e] = x[src];
}

__global__ void cls_init_kernel(const float* __restrict__ cls_token,
                                const float* __restrict__ pos_embed) {
    int gid = blockIdx.x * blockDim.x + threadIdx.x;
    if (gid >= BATCH * EMB) return;
    int b = gid / EMB;
    int e = gid - b * EMB;
    g_t[(size_t)b * NTOK * EMB + e] = cls_token[e] + pos_embed[e];
}

// ---------------- 3xBF16 tensor-core GEMM: C[M,N] = A[M,K] * W[N,K]^T ----------------
// Each fp32 split into bf16 hi+lo; C += ah*bh + ah*bl + al*bh (eff ~16-17 mantissa bits).
// m16n8k16 bf16 MMA: 2048 MACs/instr -> half the instruction count of 3xTF32.
// EPI: 0 = bias, 1 = bias+GELU, 2 = bias+residual add, 3 = patch scatter + pos_embed
#define GBM 128
#define GBN 128
#define GBK 16
#define WSTR 12      // words (bf16x2) per row: 8 used + 4 pad -> 12g+tg covers all 32 banks

template<int EPI>
__global__ void __launch_bounds__(256, 2)
gemm_tc(const float* __restrict__ A, const float* __restrict__ W,
        const float* __restrict__ bias, float* __restrict__ C,
        int M, int N, int K, const float* __restrict__ extra)
{
    __shared__ unsigned AsH[GBM * WSTR];
    __shared__ unsigned AsL[GBM * WSTR];
    __shared__ unsigned BsH[GBN * WSTR];
    __shared__ unsigned BsL[GBN * WSTR];

    const int tid  = threadIdx.x;
    const int lane = tid & 31;
    const int warp = tid >> 5;
    const int wm = (warp & 3) * 32;    // warp row offset
    const int wn = (warp >> 2) * 64;   // warp col offset
    const int bm = blockIdx.y * GBM;
    const int bn = blockIdx.x * GBN;
    const int g  = lane >> 2;          // 0..7
    const int tg = lane & 3;           // 0..3

    // global->smem load mapping: 2 rows of A and W per thread per k-tile
    const int r0 = tid >> 2;           // 0..63
    const int r1 = r0 + 64;            // 64..127
    const int c4 = (tid & 3) * 4;      // k offset 0,4,8,12
    const int w0 = 2 * (tid & 3);      // packed word offset 0,2,4,6

    float c[2][8][4];
    #pragma unroll
    for (int i = 0; i < 2; i++)
        #pragma unroll
        for (int j = 0; j < 8; j++)
            #pragma unroll
            for (int v = 0; v < 4; v++) c[i][j][v] = 0.f;

    const float4 z4 = make_float4(0.f, 0.f, 0.f, 0.f);
    float4 av0, av1, wv0, wv1;

    // prologue: fetch k-tile 0
    av0 = (bm + r0 < M) ? *(const float4*)&A[(size_t)(bm + r0) * K + c4] : z4;
    av1 = (bm + r1 < M) ? *(const float4*)&A[(size_t)(bm + r1) * K + c4] : z4;
    wv0 = *(const float4*)&W[(size_t)(bn + r0) * K + c4];
    wv1 = *(const float4*)&W[(size_t)(bn + r1) * K + c4];

    const int nIter = K >> 4;
    for (int it = 0; it < nIter; it++) {
        // ---- registers -> smem (bf16 hi/lo split, packed bf16x2 words) ----
        {
            unsigned h0, h1, l0, l1;
            split_pair(av0.x, av0.y, h0, l0); split_pair(av0.z, av0.w, h1, l1);
            *(uint2*)&AsH[r0 * WSTR + w0] = make_uint2(h0, h1);
            *(uint2*)&AsL[r0 * WSTR + w0] = make_uint2(l0, l1);
            split_pair(av1.x, av1.y, h0, l0); split_pair(av1.z, av1.w, h1, l1);
            *(uint2*)&AsH[r1 * WSTR + w0] = make_uint2(h0, h1);
            *(uint2*)&AsL[r1 * WSTR + w0] = make_uint2(l0, l1);
            split_pair(wv0.x, wv0.y, h0, l0); split_pair(wv0.z, wv0.w, h1, l1);
            *(uint2*)&BsH[r0 * WSTR + w0] = make_uint2(h0, h1);
            *(uint2*)&BsL[r0 * WSTR + w0] = make_uint2(l0, l1);
            split_pair(wv1.x, wv1.y, h0, l0); split_pair(wv1.z, wv1.w, h1, l1);
            *(uint2*)&BsH[r1 * WSTR + w0] = make_uint2(h0, h1);
            *(uint2*)&BsL[r1 * WSTR + w0] = make_uint2(l0, l1);
        }
        __syncthreads();

        // ---- prefetch next k-tile globals (overlaps with MMA below) ----
        if (it + 1 < nIter) {
            int k0 = (it + 1) << 4;
            av0 = (bm + r0 < M) ? *(const float4*)&A[(size_t)(bm + r0) * K + k0 + c4] : z4;
            av1 = (bm + r1 < M) ? *(const float4*)&A[(size_t)(bm + r1) * K + k0 + c4] : z4;
            wv0 = *(const float4*)&W[(size_t)(bn + r0) * K + k0 + c4];
            wv1 = *(const float4*)&W[(size_t)(bn + r1) * K + k0 + c4];
        }

        // ---- compute: one m16n8k16 k-step covers the whole k-tile ----
        unsigned aH[2][4], aL[2][4];
        #pragma unroll
        for (int i = 0; i < 2; i++) {
            int row = wm + i * 16 + g;
            aH[i][0] = AsH[row * WSTR + tg];
            aH[i][1] = AsH[(row + 8) * WSTR + tg];
            aH[i][2] = AsH[row * WSTR + tg + 4];
            aH[i][3] = AsH[(row + 8) * WSTR + tg + 4];
            aL[i][0] = AsL[row * WSTR + tg];
            aL[i][1] = AsL[(row + 8) * WSTR + tg];
            aL[i][2] = AsL[row * WSTR + tg + 4];
            aL[i][3] = AsL[(row + 8) * WSTR + tg + 4];
        }
        #pragma unroll
        for (int j = 0; j < 8; j++) {
            int col = wn + j * 8 + g;
            unsigned bh0 = BsH[col * WSTR + tg];
            unsigned bh1 = BsH[col * WSTR + tg + 4];
            unsigned bl0 = BsL[col * WSTR + tg];
            unsigned bl1 = BsL[col * WSTR + tg + 4];
            #pragma unroll
            for (int i = 0; i < 2; i++) {
                mma_bf16(c[i][j], aH[i], bh0, bh1);   // hi*hi
                mma_bf16(c[i][j], aH[i], bl0, bl1);   // hi*lo
                mma_bf16(c[i][j], aL[i], bh0, bh1);   // lo*hi
            }
        }
        __syncthreads();
    }

    // ---- epilogue ----
    #pragma unroll
    for (int i = 0; i < 2; i++) {
        #pragma unroll
        for (int half = 0; half < 2; half++) {
            int r = bm + wm + i * 16 + g + half * 8;
            if (r >= M) continue;
            #pragma unroll
            for (int j = 0; j < 8; j++) {
                int col = bn + wn + j * 8 + tg * 2;
                float v0 = c[i][j][half * 2 + 0] + bias[col];
                float v1 = c[i][j][half * 2 + 1] + bias[col + 1];
                if (EPI == 0) {
                    C[(size_t)r * N + col]     = v0;
                    C[(size_t)r * N + col + 1] = v1;
                } else if (EPI == 1) {
                    C[(size_t)r * N + col]     = 0.5f * v0 * (1.0f + erff(v0 * 0.70710678118654752f));
                    C[(size_t)r * N + col + 1] = 0.5f * v1 * (1.0f + erff(v1 * 0.70710678118654752f));
                } else if (EPI == 2) {
                    size_t o = (size_t)r * N + col;
                    C[o]     += v0;
                    C[o + 1] += v1;
                } else { // patch scatter
                    int b = r / NPATCH;
                    int p = r - b * NPATCH;
                    size_t o = ((size_t)b * NTOK + 1 + p) * EMB + col;
                    C[o]     = v0 + extra[(size_t)(1 + p) * EMB + col];
                    C[o + 1] = v1 + extra[(size_t)(1 + p) * EMB + col + 1];
                }
            }
        }
    }
}

// ---------------- LayerNorm ----------------
__global__ void ln_kernel(const float* __restrict__ x, const float* __restrict__ w,
                          const float* __restrict__ bvec, float* __restrict__ y) {
    const int row = blockIdx.x;
    const float* xr = x + (size_t)row * EMB;
    const int tid = threadIdx.x;           // 128
    float s = 0.f, s2 = 0.f;
    #pragma unroll
    for (int e = tid; e < EMB; e += 128) {
        float v = xr[e];
        s += v; s2 += v * v;
    }
    #pragma unroll
    for (int o = 16; o; o >>= 1) {
        s  += __shfl_xor_sync(0xffffffffu, s,  o);
        s2 += __shfl_xor_sync(0xffffffffu, s2, o);
    }
    __shared__ float r1[4], r2[4];
    if ((tid & 31) == 0) { r1[tid >> 5] = s; r2[tid >> 5] = s2; }
    __syncthreads();
    float S  = r1[0] + r1[1] + r1[2] + r1[3];
    float S2 = r2[0] + r2[1] + r2[2] + r2[3];
    float mu = S * (1.0f / EMB);
    float var = S2 * (1.0f / EMB) - mu * mu;
    float rs = rsqrtf(var + 1e-5f);
    float* yr = y + (size_t)row * EMB;
    #pragma unroll
    for (int e = tid; e < EMB; e += 128)
        yr[e] = (xr[e] - mu) * rs * w[e] + bvec[e];
}

// ---------------- flash attention: block = (64 queries, one (b,h)) ----------------
#define QT 64
#define KT 48
#define AST 52     // padded row stride (floats): 16B-aligned, conflict-free

__global__ void __launch_bounds__(256, 1)
attn_flash(const float* __restrict__ qkv, float* __restrict__ out) {
    __shared__ float Qs[QT * AST];
    __shared__ float Ks[KT * AST];
    __shared__ float Vs[KT * AST];
    __shared__ float Ps[QT * AST];

    const int tid = threadIdx.x;
    const int h = blockIdx.y, b = blockIdx.z;
    const int qbase = blockIdx.x * QT;
    const int q   = tid >> 2;     // 0..63 query within tile
    const int sub = tid & 3;      // quad lane

    // ---- load Q tile (64 x 48), coalesced float4 ----
    #pragma unroll
    for (int l = 0; l < 3; l++) {
        int idx = tid + 256 * l;          // 0..767
        int row = idx / 12, cc = idx % 12;
        int gq = qbase + row;
        float4 v = (gq < NTOK)
            ? *(const float4*)&qkv[((size_t)(b * NTOK + gq)) * QKVD + h * HD + cc * 4]
            : make_float4(0.f, 0.f, 0.f, 0.f);
        *(float4*)&Qs[row * AST + cc * 4] = v;
    }

    const float scale = 0.14433756729740643f;  // 1/sqrt(48)
    float m = -1e30f, l_sum = 0.f;
    float acc[12];
    #pragma unroll
    for (int j = 0; j < 12; j++) acc[j] = 0.f;

    const int ntiles = (NTOK + KT - 1) / KT;   // 37
    for (int t0 = 0; t0 < ntiles; t0++) {
        const int kbase = t0 * KT;
        __syncthreads();   // protect Ks/Vs/Ps from prior-iteration readers
        // ---- load K,V tiles (48 x 48 each), coalesced ----
        #pragma unroll
        for (int l = 0; l < 3; l++) {
            int idx = tid + 256 * l;
            if (idx < KT * 12) {
                int row = idx / 12, cc = idx % 12;
                int gk = kbase + row;
                float4 kv, vv;
                if (gk < NTOK) {
                    size_t base = ((size_t)(b * NTOK + gk)) * QKVD + h * HD;
                    kv = *(const float4*)&qkv[base + EMB + cc * 4];
                    vv = *(const float4*)&qkv[base + 2 * EMB + cc * 4];
                } else {
                    kv = make_float4(0.f, 0.f, 0.f, 0.f);
                    vv = kv;
                }
                *(float4*)&Ks[row * AST + cc * 4] = kv;
                *(float4*)&Vs[row * AST + cc * 4] = vv;
            }
        }
        __syncthreads();

        // ---- scores: this thread handles 12 keys k = sub + 4*kk ----
        float s[12];
        #pragma unroll
        for (int kk = 0; kk < 12; kk++) s[kk] = 0.f;
        #pragma unroll
        for (int d4 = 0; d4 < 12; d4++) {
            float4 qd = *(const float4*)&Qs[q * AST + d4 * 4];
            #pragma unroll
            for (int kk = 0; kk < 12; kk++) {
                int k = sub + 4 * kk;
                float4 kd = *(const float4*)&Ks[k * AST + d4 * 4];
                s[kk] += qd.x * kd.x + qd.y * kd.y + qd.z * kd.z + qd.w * kd.w;
            }
        }
        float tmax = -1e30f;
        #pragma unroll
        for (int kk = 0; kk < 12; kk++) {
            int k = sub + 4 * kk;
            s[kk] = (kbase + k < NTOK) ? s[kk] * scale : -1e30f;
            tmax = fmaxf(tmax, s[kk]);
        }
        tmax = fmaxf(tmax, __shfl_xor_sync(0xffffffffu, tmax, 1));
        tmax = fmaxf(tmax, __shfl_xor_sync(0xffffffffu, tmax, 2));
        float mnew = fmaxf(m, tmax);
        float alpha = __expf(m - mnew);
        float psum = 0.f;
        #pragma unroll
        for (int kk = 0; kk < 12; kk++) {
            float p = __expf(s[kk] - mnew);
            psum += p;
            Ps[q * AST + sub + 4 * kk] = p;
        }
        psum += __shfl_xor_sync(0xffffffffu, psum, 1);
        psum += __shfl_xor_sync(0xffffffffu, psum, 2);
        l_sum = l_sum * alpha + psum;
        m = mnew;
        #pragma unroll
        for (int j = 0; j < 12; j++) acc[j] *= alpha;
        __syncthreads();   // Ps visible to all quad members

        // ---- P @ V : this thread owns dims d0..d0+11 of query q ----
        const int d0 = sub * 12;
        #pragma unroll 4
        for (int k = 0; k < KT; k++) {
            float p = Ps[q * AST + k];
            float4 v0 = *(const float4*)&Vs[k * AST + d0];
            float4 v1 = *(const float4*)&Vs[k * AST + d0 + 4];
            float4 v2 = *(const float4*)&Vs[k * AST + d0 + 8];
            acc[0] += p * v0.x; acc[1] += p * v0.y; acc[2]  += p * v0.z; acc[3]  += p * v0.w;
            acc[4] += p * v1.x; acc[5] += p * v1.y; acc[6]  += p * v1.z; acc[7]  += p * v1.w;
            acc[8] += p * v2.x; acc[9] += p * v2.y; acc[10] += p * v2.z; acc[11] += p * v2.w;
        }
    }

    int gq = qbase + q;
    if (gq < NTOK) {
        float inv = 1.0f / l_sum;
        size_t o = ((size_t)(b * NTOK + gq)) * EMB + h * HD + sub * 12;
        #pragma unroll
        for (int j = 0; j < 12; j++) out[o + j] = acc[j] * inv;
    }
}

// ---------------- final LN(cls) + head ----------------
__global__ void head_kernel(const float* __restrict__ t, const float* __restrict__ nw,
                            const float* __restrict__ nb, const float* __restrict__ hw,
                            const float* __restrict__ hb, float* __restrict__ out) {
    const int b = blockIdx.x;
    const float* xr = t + (size_t)b * NTOK * EMB;
    const int tid = threadIdx.x;
    float s = 0.f, s2 = 0.f;
    for (int e = tid; e < EMB; e += 128) { float v = xr[e]; s += v; s2 += v * v; }
    #pragma unroll
    for (int o = 16; o; o >>= 1) {
        s  += __shfl_xor_sync(0xffffffffu, s,  o);
        s2 += __shfl_xor_sync(0xffffffffu, s2, o);
    }
    __shared__ float r1[4], r2[4], rd0[4], rd1[4];
    if ((tid & 31) == 0) { r1[tid >> 5] = s; r2[tid >> 5] = s2; }
    __syncthreads();
    float S  = r1[0] + r1[1] + r1[2] + r1[3];
    float S2 = r2[0] + r2[1] + r2[2] + r2[3];
    float mu = S * (1.0f / EMB);
    float rs = rsqrtf(S2 * (1.0f / EMB) - mu * mu + 1e-5f);
    float d0 = 0.f, d1 = 0.f;
    for (int e = tid; e < EMB; e += 128) {
        float nv = (xr[e] - mu) * rs * nw[e] + nb[e];
        d0 += nv * hw[e];
        d1 += nv * hw[EMB + e];
    }
    #pragma unroll
    for (int o = 16; o; o >>= 1) {
        d0 += __shfl_xor_sync(0xffffffffu, d0, o);
        d1 += __shfl_xor_sync(0xffffffffu, d1, o);
    }
    if ((tid & 31) == 0) { rd0[tid >> 5] = d0; rd1[tid >> 5] = d1; }
    __syncthreads();
    if (tid == 0) {
        out[b * NC + 0] = rd0[0] + rd0[1] + rd0[2] + rd0[3] + hb[0];
        out[b * NC + 1] = rd1[0] + rd1[1] + rd1[2] + rd1[3] + hb[1];
    }
}

// ---------------- host orchestration ----------------
extern "C" void kernel_launch(void* const* d_in, const int* in_sizes, int n_in,
                              void* d_out, int out_size) {
    const float* x         = (const float*)d_in[0];
    const float* conv_w    = (const float*)d_in[1];
    const float* conv_b    = (const float*)d_in[2];
    const float* cls_token = (const float*)d_in[3];
    const float* pos_embed = (const float*)d_in[4];
    const float* ln1_w     = (const float*)d_in[5];
    const float* ln1_b     = (const float*)d_in[6];
    const float* qkv_w     = (const float*)d_in[7];
    const float* qkv_b     = (const float*)d_in[8];
    const float* proj_w    = (const float*)d_in[9];
    const float* proj_b    = (const float*)d_in[10];
    const float* ln2_w     = (const float*)d_in[11];
    const float* ln2_b     = (const float*)d_in[12];
    const float* mlp_w1    = (const float*)d_in[13];
    const float* mlp_b1    = (const float*)d_in[14];
    const float* mlp_w2    = (const float*)d_in[15];
    const float* mlp_b2    = (const float*)d_in[16];
    const float* norm_w    = (const float*)d_in[17];
    const float* norm_b    = (const float*)d_in[18];
    const float* head_w    = (const float*)d_in[19];
    const float* head_b    = (const float*)d_in[20];
    float* out = (float*)d_out;

    float *patches, *t, *h, *qkv, *attno, *mlp;
    cudaGetSymbolAddress((void**)&patches, g_patches);
    cudaGetSymbolAddress((void**)&t,       g_t);
    cudaGetSymbolAddress((void**)&h,       g_h);
    cudaGetSymbolAddress((void**)&qkv,     g_qkv);
    cudaGetSymbolAddress((void**)&attno,   g_attno);
    cudaGetSymbolAddress((void**)&mlp,     g_mlp);

    const int Mtok = BATCH * NTOK;   // 3458
    const int Mpat = BATCH * NPATCH; // 3456
    const int MtokBlocks = (Mtok + GBM - 1) / GBM;  // 28

    // 1) patchify + patch-embed GEMM + cls
    {
        int total = BATCH * NPATCH * PK;
        patchify_kernel<<<(total + 255) / 256, 256>>>(x);
        dim3 grid(EMB / GBN, Mpat / GBM);
        gemm_tc<3><<<grid, 256>>>(patches, conv_w, conv_b, t, Mpat, EMB, PK, pos_embed);
        cls_init_kernel<<<(BATCH * EMB + 255) / 256, 256>>>(cls_token, pos_embed);
    }

    // 2) transformer layers
    for (int i = 0; i < NL; i++) {
        ln_kernel<<<Mtok, 128>>>(t, ln1_w + i * EMB, ln1_b + i * EMB, h);
        {
            dim3 grid(QKVD / GBN, MtokBlocks);
            gemm_tc<0><<<grid, 256>>>(h, qkv_w + (size_t)i * QKVD * EMB,
                                      qkv_b + i * QKVD, qkv, Mtok, QKVD, EMB, nullptr);
        }
        {
            dim3 grid((NTOK + QT - 1) / QT, NH, BATCH);
            attn_flash<<<grid, 256>>>(qkv, attno);
        }
        {
            dim3 grid(EMB / GBN, MtokBlocks);
            gemm_tc<2><<<grid, 256>>>(attno, proj_w + (size_t)i * EMB * EMB,
                                      proj_b + i * EMB, t, Mtok, EMB, EMB, nullptr);
        }
        ln_kernel<<<Mtok, 128>>>(t, ln2_w + i * EMB, ln2_b + i * EMB, h);
        {
            dim3 grid(MLPD / GBN, MtokBlocks);
            gemm_tc<1><<<grid, 256>>>(h, mlp_w1 + (size_t)i * MLPD * EMB,
                                      mlp_b1 + i * MLPD, mlp, Mtok, MLPD, EMB, nullptr);
        }
        {
            dim3 grid(EMB / GBN, MtokBlocks);
            gemm_tc<2><<<grid, 256>>>(mlp, mlp_w2 + (size_t)i * EMB * MLPD,
                                      mlp_b2 + i * EMB, t, Mtok, EMB, MLPD, nullptr);
        }
    }

    // 3) head
    head_kernel<<<BATCH, 128>>>(t, norm_w, norm_b, head_w, head_b, out);
}

// round 12
// speedup vs baseline: 17.2414x; 1.0001x over previous
#include <cuda_runtime.h>
#include <cuda_bf16.h>
#include <math.h>

// ---------------- problem constants ----------------
#define BATCH   2
#define IMG     96
#define PP      8
#define EMB     384
#define NH      8
#define HD      48
#define NL      6
#define MLPD    1536
#define NC      2
#define NPATCH  1728            // (96/8)^3
#define NTOK    1729            // NPATCH + 1
#define PK      512             // P^3 * CIN
#define QKVD    1152            // 3*EMB

// ---------------- device scratch (static, allocation-free) ----------------
__device__ float g_patches[BATCH * NPATCH * PK];
__device__ float g_t     [BATCH * NTOK * EMB];
__device__ float g_h     [BATCH * NTOK * EMB];
__device__ float g_qkv   [BATCH * NTOK * QKVD];
__device__ float g_attno [BATCH * NTOK * EMB];
__device__ float g_mlp   [BATCH * NTOK * MLPD];

// ---------------- small helpers ----------------
// split fp32 pair into packed bf16x2 hi and lo words (hi+lo ~ 16-17 mantissa bits)
__device__ __forceinline__ void split_pair(float x, float y, unsigned &hi, unsigned &lo) {
    __nv_bfloat16 hx = __float2bfloat16(x);
    __nv_bfloat16 hy = __float2bfloat16(y);
    hi = ((unsigned)__bfloat16_as_ushort(hy) << 16) | (unsigned)__bfloat16_as_ushort(hx);
    float rx = x - __bfloat162float(hx);
    float ry = y - __bfloat162float(hy);
    __nv_bfloat16 lx = __float2bfloat16(rx);
    __nv_bfloat16 ly = __float2bfloat16(ry);
    lo = ((unsigned)__bfloat16_as_ushort(ly) << 16) | (unsigned)__bfloat16_as_ushort(lx);
}

__device__ __forceinline__ void mma_bf16(float c[4], const unsigned a[4],
                                         unsigned b0, unsigned b1) {
    asm volatile(
        "mma.sync.aligned.m16n8k16.row.col.f32.bf16.bf16.f32 "
        "{%0,%1,%2,%3}, {%4,%5,%6,%7}, {%8,%9}, {%0,%1,%2,%3};"
        : "+f"(c[0]), "+f"(c[1]), "+f"(c[2]), "+f"(c[3])
        : "r"(a[0]), "r"(a[1]), "r"(a[2]), "r"(a[3]), "r"(b0), "r"(b1));
}

// ---------------- patchify ----------------
__global__ void patchify_kernel(const float* __restrict__ x) {
    int gid = blockIdx.x * blockDim.x + threadIdx.x;
    const int total = BATCH * NPATCH * PK;
    if (gid >= total) return;
    int e = gid & (PK - 1);
    int r = gid >> 9;
    int b = r / NPATCH;
    int p = r - b * NPATCH;
    int pz = p / 144;
    int py = (p / 12) % 12;
    int px = p % 12;
    int i = e >> 6;
    int j = (e >> 3) & 7;
    int k = e & 7;
    size_t src = (size_t)b * IMG * IMG * IMG
               + (size_t)(pz * PP + i) * IMG * IMG
               + (size_t)(py * PP + j) * IMG
               + (px * PP + k);
    g_patches[(size_t)r * PK + e] = x[src];
}

__global__ void cls_init_kernel(const float* __restrict__ cls_token,
                                const float* __restrict__ pos_embed) {
    int gid = blockIdx.x * blockDim.x + threadIdx.x;
    if (gid >= BATCH * EMB) return;
    int b = gid / EMB;
    int e = gid - b * EMB;
    g_t[(size_t)b * NTOK * EMB + e] = cls_token[e] + pos_embed[e];
}

// ---------------- 3xBF16 tensor-core GEMM: C[M,N] = A[M,K] * W[N,K]^T ----------------
// Each fp32 split into bf16 hi+lo; C += ah*bh + ah*bl + al*bh (eff ~16-17 mantissa bits).
// m16n8k16 bf16 MMA: 2048 MACs/instr -> half the instruction count of 3xTF32.
// EPI: 0 = bias, 1 = bias+GELU, 2 = bias+residual add, 3 = patch scatter + pos_embed
#define GBM 128
#define GBN 128
#define GBK 16
#define WSTR 12      // words (bf16x2) per row: 8 used + 4 pad -> 12g+tg covers all 32 banks

template<int EPI>
__global__ void __launch_bounds__(256, 2)
gemm_tc(const float* __restrict__ A, const float* __restrict__ W,
        const float* __restrict__ bias, float* __restrict__ C,
        int M, int N, int K, const float* __restrict__ extra)
{
    __shared__ unsigned AsH[GBM * WSTR];
    __shared__ unsigned AsL[GBM * WSTR];
    __shared__ unsigned BsH[GBN * WSTR];
    __shared__ unsigned BsL[GBN * WSTR];

    const int tid  = threadIdx.x;
    const int lane = tid & 31;
    const int warp = tid >> 5;
    const int wm = (warp & 3) * 32;    // warp row offset
    const int wn = (warp >> 2) * 64;   // warp col offset
    const int bm = blockIdx.y * GBM;
    const int bn = blockIdx.x * GBN;
    const int g  = lane >> 2;          // 0..7
    const int tg = lane & 3;           // 0..3

    // global->smem load mapping: 2 rows of A and W per thread per k-tile
    const int r0 = tid >> 2;           // 0..63
    const int r1 = r0 + 64;            // 64..127
    const int c4 = (tid & 3) * 4;      // k offset 0,4,8,12
    const int w0 = 2 * (tid & 3);      // packed word offset 0,2,4,6

    float c[2][8][4];
    #pragma unroll
    for (int i = 0; i < 2; i++)
        #pragma unroll
        for (int j = 0; j < 8; j++)
            #pragma unroll
            for (int v = 0; v < 4; v++) c[i][j][v] = 0.f;

    const float4 z4 = make_float4(0.f, 0.f, 0.f, 0.f);
    float4 av0, av1, wv0, wv1;

    // prologue: fetch k-tile 0
    av0 = (bm + r0 < M) ? *(const float4*)&A[(size_t)(bm + r0) * K + c4] : z4;
    av1 = (bm + r1 < M) ? *(const float4*)&A[(size_t)(bm + r1) * K + c4] : z4;
    wv0 = *(const float4*)&W[(size_t)(bn + r0) * K + c4];
    wv1 = *(const float4*)&W[(size_t)(bn + r1) * K + c4];

    const int nIter = K >> 4;
    for (int it = 0; it < nIter; it++) {
        // ---- registers -> smem (bf16 hi/lo split, packed bf16x2 words) ----
        {
            unsigned h0, h1, l0, l1;
            split_pair(av0.x, av0.y, h0, l0); split_pair(av0.z, av0.w, h1, l1);
            *(uint2*)&AsH[r0 * WSTR + w0] = make_uint2(h0, h1);
            *(uint2*)&AsL[r0 * WSTR + w0] = make_uint2(l0, l1);
            split_pair(av1.x, av1.y, h0, l0); split_pair(av1.z, av1.w, h1, l1);
            *(uint2*)&AsH[r1 * WSTR + w0] = make_uint2(h0, h1);
            *(uint2*)&AsL[r1 * WSTR + w0] = make_uint2(l0, l1);
            split_pair(wv0.x, wv0.y, h0, l0); split_pair(wv0.z, wv0.w, h1, l1);
            *(uint2*)&BsH[r0 * WSTR + w0] = make_uint2(h0, h1);
            *(uint2*)&BsL[r0 * WSTR + w0] = make_uint2(l0, l1);
            split_pair(wv1.x, wv1.y, h0, l0); split_pair(wv1.z, wv1.w, h1, l1);
            *(uint2*)&BsH[r1 * WSTR + w0] = make_uint2(h0, h1);
            *(uint2*)&BsL[r1 * WSTR + w0] = make_uint2(l0, l1);
        }
        __syncthreads();

        // ---- prefetch next k-tile globals (overlaps with MMA below) ----
        if (it + 1 < nIter) {
            int k0 = (it + 1) << 4;
            av0 = (bm + r0 < M) ? *(const float4*)&A[(size_t)(bm + r0) * K + k0 + c4] : z4;
            av1 = (bm + r1 < M) ? *(const float4*)&A[(size_t)(bm + r1) * K + k0 + c4] : z4;
            wv0 = *(const float4*)&W[(size_t)(bn + r0) * K + k0 + c4];
            wv1 = *(const float4*)&W[(size_t)(bn + r1) * K + k0 + c4];
        }

        // ---- compute: one m16n8k16 k-step covers the whole k-tile ----
        unsigned aH[2][4], aL[2][4];
        #pragma unroll
        for (int i = 0; i < 2; i++) {
            int row = wm + i * 16 + g;
            aH[i][0] = AsH[row * WSTR + tg];
            aH[i][1] = AsH[(row + 8) * WSTR + tg];
            aH[i][2] = AsH[row * WSTR + tg + 4];
            aH[i][3] = AsH[(row + 8) * WSTR + tg + 4];
            aL[i][0] = AsL[row * WSTR + tg];
            aL[i][1] = AsL[(row + 8) * WSTR + tg];
            aL[i][2] = AsL[row * WSTR + tg + 4];
            aL[i][3] = AsL[(row + 8) * WSTR + tg + 4];
        }
        #pragma unroll
        for (int j = 0; j < 8; j++) {
            int col = wn + j * 8 + g;
            unsigned bh0 = BsH[col * WSTR + tg];
            unsigned bh1 = BsH[col * WSTR + tg + 4];
            unsigned bl0 = BsL[col * WSTR + tg];
            unsigned bl1 = BsL[col * WSTR + tg + 4];
            #pragma unroll
            for (int i = 0; i < 2; i++) {
                mma_bf16(c[i][j], aH[i], bh0, bh1);   // hi*hi
                mma_bf16(c[i][j], aH[i], bl0, bl1);   // hi*lo
                mma_bf16(c[i][j], aL[i], bh0, bh1);   // lo*hi
            }
        }
        __syncthreads();
    }

    // ---- epilogue ----
    #pragma unroll
    for (int i = 0; i < 2; i++) {
        #pragma unroll
        for (int half = 0; half < 2; half++) {
            int r = bm + wm + i * 16 + g + half * 8;
            if (r >= M) continue;
            #pragma unroll
            for (int j = 0; j < 8; j++) {
                int col = bn + wn + j * 8 + tg * 2;
                float v0 = c[i][j][half * 2 + 0] + bias[col];
                float v1 = c[i][j][half * 2 + 1] + bias[col + 1];
                if (EPI == 0) {
                    C[(size_t)r * N + col]     = v0;
                    C[(size_t)r * N + col + 1] = v1;
                } else if (EPI == 1) {
                    C[(size_t)r * N + col]     = 0.5f * v0 * (1.0f + erff(v0 * 0.70710678118654752f));
                    C[(size_t)r * N + col + 1] = 0.5f * v1 * (1.0f + erff(v1 * 0.70710678118654752f));
                } else if (EPI == 2) {
                    size_t o = (size_t)r * N + col;
                    C[o]     += v0;
                    C[o + 1] += v1;
                } else { // patch scatter
                    int b = r / NPATCH;
                    int p = r - b * NPATCH;
                    size_t o = ((size_t)b * NTOK + 1 + p) * EMB + col;
                    C[o]     = v0 + extra[(size_t)(1 + p) * EMB + col];
                    C[o + 1] = v1 + extra[(size_t)(1 + p) * EMB + col + 1];
                }
            }
        }
    }
}

// ---------------- LayerNorm ----------------
__global__ void ln_kernel(const float* __restrict__ x, const float* __restrict__ w,
                          const float* __restrict__ bvec, float* __restrict__ y) {
    const int row = blockIdx.x;
    const float* xr = x + (size_t)row * EMB;
    const int tid = threadIdx.x;           // 128
    float s = 0.f, s2 = 0.f;
    #pragma unroll
    for (int e = tid; e < EMB; e += 128) {
        float v = xr[e];
        s += v; s2 += v * v;
    }
    #pragma unroll
    for (int o = 16; o; o >>= 1) {
        s  += __shfl_xor_sync(0xffffffffu, s,  o);
        s2 += __shfl_xor_sync(0xffffffffu, s2, o);
    }
    __shared__ float r1[4], r2[4];
    if ((tid & 31) == 0) { r1[tid >> 5] = s; r2[tid >> 5] = s2; }
    __syncthreads();
    float S  = r1[0] + r1[1] + r1[2] + r1[3];
    float S2 = r2[0] + r2[1] + r2[2] + r2[3];
    float mu = S * (1.0f / EMB);
    float var = S2 * (1.0f / EMB) - mu * mu;
    float rs = rsqrtf(var + 1e-5f);
    float* yr = y + (size_t)row * EMB;
    #pragma unroll
    for (int e = tid; e < EMB; e += 128)
        yr[e] = (xr[e] - mu) * rs * w[e] + bvec[e];
}

// ---------------- flash attention: block = (64 queries, one (b,h)) ----------------
#define QT 64
#define KT 48
#define AST 52     // padded row stride (floats): 16B-aligned, conflict-free

__global__ void __launch_bounds__(256, 1)
attn_flash(const float* __restrict__ qkv, float* __restrict__ out) {
    __shared__ float Qs[QT * AST];
    __shared__ float Ks[KT * AST];
    __shared__ float Vs[KT * AST];
    __shared__ float Ps[QT * AST];

    const int tid = threadIdx.x;
    const int h = blockIdx.y, b = blockIdx.z;
    const int qbase = blockIdx.x * QT;
    const int q   = tid >> 2;     // 0..63 query within tile
    const int sub = tid & 3;      // quad lane

    // ---- load Q tile (64 x 48), coalesced float4 ----
    #pragma unroll
    for (int l = 0; l < 3; l++) {
        int idx = tid + 256 * l;          // 0..767
        int row = idx / 12, cc = idx % 12;
        int gq = qbase + row;
        float4 v = (gq < NTOK)
            ? *(const float4*)&qkv[((size_t)(b * NTOK + gq)) * QKVD + h * HD + cc * 4]
            : make_float4(0.f, 0.f, 0.f, 0.f);
        *(float4*)&Qs[row * AST + cc * 4] = v;
    }

    const float scale = 0.14433756729740643f;  // 1/sqrt(48)
    float m = -1e30f, l_sum = 0.f;
    float acc[12];
    #pragma unroll
    for (int j = 0; j < 12; j++) acc[j] = 0.f;

    const int ntiles = (NTOK + KT - 1) / KT;   // 37
    for (int t0 = 0; t0 < ntiles; t0++) {
        const int kbase = t0 * KT;
        __syncthreads();   // protect Ks/Vs/Ps from prior-iteration readers
        // ---- load K,V tiles (48 x 48 each), coalesced ----
        #pragma unroll
        for (int l = 0; l < 3; l++) {
            int idx = tid + 256 * l;
            if (idx < KT * 12) {
                int row = idx / 12, cc = idx % 12;
                int gk = kbase + row;
                float4 kv, vv;
                if (gk < NTOK) {
                    size_t base = ((size_t)(b * NTOK + gk)) * QKVD + h * HD;
                    kv = *(const float4*)&qkv[base + EMB + cc * 4];
                    vv = *(const float4*)&qkv[base + 2 * EMB + cc * 4];
                } else {
                    kv = make_float4(0.f, 0.f, 0.f, 0.f);
                    vv = kv;
                }
                *(float4*)&Ks[row * AST + cc * 4] = kv;
                *(float4*)&Vs[row * AST + cc * 4] = vv;
            }
        }
        __syncthreads();

        // ---- scores: this thread handles 12 keys k = sub + 4*kk ----
        float s[12];
        #pragma unroll
        for (int kk = 0; kk < 12; kk++) s[kk] = 0.f;
        #pragma unroll
        for (int d4 = 0; d4 < 12; d4++) {
            float4 qd = *(const float4*)&Qs[q * AST + d4 * 4];
            #pragma unroll
            for (int kk = 0; kk < 12; kk++) {
                int k = sub + 4 * kk;
                float4 kd = *(const float4*)&Ks[k * AST + d4 * 4];
                s[kk] += qd.x * kd.x + qd.y * kd.y + qd.z * kd.z + qd.w * kd.w;
            }
        }
        float tmax = -1e30f;
        #pragma unroll
        for (int kk = 0; kk < 12; kk++) {
            int k = sub + 4 * kk;
            s[kk] = (kbase + k < NTOK) ? s[kk] * scale : -1e30f;
            tmax = fmaxf(tmax, s[kk]);
        }
        tmax = fmaxf(tmax, __shfl_xor_sync(0xffffffffu, tmax, 1));
        tmax = fmaxf(tmax, __shfl_xor_sync(0xffffffffu, tmax, 2));
        float mnew = fmaxf(m, tmax);
        float alpha = __expf(m - mnew);
        float psum = 0.f;
        #pragma unroll
        for (int kk = 0; kk < 12; kk++) {
            float p = __expf(s[kk] - mnew);
            psum += p;
            Ps[q * AST + sub + 4 * kk] = p;
        }
        psum += __shfl_xor_sync(0xffffffffu, psum, 1);
        psum += __shfl_xor_sync(0xffffffffu, psum, 2);
        l_sum = l_sum * alpha + psum;
        m = mnew;
        #pragma unroll
        for (int j = 0; j < 12; j++) acc[j] *= alpha;
        __syncthreads();   // Ps visible to all quad members

        // ---- P @ V : this thread owns dims d0..d0+11 of query q ----
        const int d0 = sub * 12;
        #pragma unroll 4
        for (int k = 0; k < KT; k++) {
            float p = Ps[q * AST + k];
            float4 v0 = *(const float4*)&Vs[k * AST + d0];
            float4 v1 = *(const float4*)&Vs[k * AST + d0 + 4];
            float4 v2 = *(const float4*)&Vs[k * AST + d0 + 8];
            acc[0] += p * v0.x; acc[1] += p * v0.y; acc[2]  += p * v0.z; acc[3]  += p * v0.w;
            acc[4] += p * v1.x; acc[5] += p * v1.y; acc[6]  += p * v1.z; acc[7]  += p * v1.w;
            acc[8] += p * v2.x; acc[9] += p * v2.y; acc[10] += p * v2.z; acc[11] += p * v2.w;
        }
    }

    int gq = qbase + q;
    if (gq < NTOK) {
        float inv = 1.0f / l_sum;
        size_t o = ((size_t)(b * NTOK + gq)) * EMB + h * HD + sub * 12;
        #pragma unroll
        for (int j = 0; j < 12; j++) out[o + j] = acc[j] * inv;
    }
}

// ---------------- final LN(cls) + head ----------------
__global__ void head_kernel(const float* __restrict__ t, const float* __restrict__ nw,
                            const float* __restrict__ nb, const float* __restrict__ hw,
                            const float* __restrict__ hb, float* __restrict__ out) {
    const int b = blockIdx.x;
    const float* xr = t + (size_t)b * NTOK * EMB;
    const int tid = threadIdx.x;
    float s = 0.f, s2 = 0.f;
    for (int e = tid; e < EMB; e += 128) { float v = xr[e]; s += v; s2 += v * v; }
    #pragma unroll
    for (int o = 16; o; o >>= 1) {
        s  += __shfl_xor_sync(0xffffffffu, s,  o);
        s2 += __shfl_xor_sync(0xffffffffu, s2, o);
    }
    __shared__ float r1[4], r2[4], rd0[4], rd1[4];
    if ((tid & 31) == 0) { r1[tid >> 5] = s; r2[tid >> 5] = s2; }
    __syncthreads();
    float S  = r1[0] + r1[1] + r1[2] + r1[3];
    float S2 = r2[0] + r2[1] + r2[2] + r2[3];
    float mu = S * (1.0f / EMB);
    float rs = rsqrtf(S2 * (1.0f / EMB) - mu * mu + 1e-5f);
    float d0 = 0.f, d1 = 0.f;
    for (int e = tid; e < EMB; e += 128) {
        float nv = (xr[e] - mu) * rs * nw[e] + nb[e];
        d0 += nv * hw[e];
        d1 += nv * hw[EMB + e];
    }
    #pragma unroll
    for (int o = 16; o; o >>= 1) {
        d0 += __shfl_xor_sync(0xffffffffu, d0, o);
        d1 += __shfl_xor_sync(0xffffffffu, d1, o);
    }
    if ((tid & 31) == 0) { rd0[tid >> 5] = d0; rd1[tid >> 5] = d1; }
    __syncthreads();
    if (tid == 0) {
        out[b * NC + 0] = rd0[0] + rd0[1] + rd0[2] + rd0[3] + hb[0];
        out[b * NC + 1] = rd1[0] + rd1[1] + rd1[2] + rd1[3] + hb[1];
    }
}

// ---------------- host orchestration ----------------
extern "C" void kernel_launch(void* const* d_in, const int* in_sizes, int n_in,
                              void* d_out, int out_size) {
    const float* x         = (const float*)d_in[0];
    const float* conv_w    = (const float*)d_in[1];
    const float* conv_b    = (const float*)d_in[2];
    const float* cls_token = (const float*)d_in[3];
    const float* pos_embed = (const float*)d_in[4];
    const float* ln1_w     = (const float*)d_in[5];
    const float* ln1_b     = (const float*)d_in[6];
    const float* qkv_w     = (const float*)d_in[7];
    const float* qkv_b     = (const float*)d_in[8];
    const float* proj_w    = (const float*)d_in[9];
    const float* proj_b    = (const float*)d_in[10];
    const float* ln2_w     = (const float*)d_in[11];
    const float* ln2_b     = (const float*)d_in[12];
    const float* mlp_w1    = (const float*)d_in[13];
    const float* mlp_b1    = (const float*)d_in[14];
    const float* mlp_w2    = (const float*)d_in[15];
    const float* mlp_b2    = (const float*)d_in[16];
    const float* norm_w    = (const float*)d_in[17];
    const float* norm_b    = (const float*)d_in[18];
    const float* head_w    = (const float*)d_in[19];
    const float* head_b    = (const float*)d_in[20];
    float* out = (float*)d_out;

    float *patches, *t, *h, *qkv, *attno, *mlp;
    cudaGetSymbolAddress((void**)&patches, g_patches);
    cudaGetSymbolAddress((void**)&t,       g_t);
    cudaGetSymbolAddress((void**)&h,       g_h);
    cudaGetSymbolAddress((void**)&qkv,     g_qkv);
    cudaGetSymbolAddress((void**)&attno,   g_attno);
    cudaGetSymbolAddress((void**)&mlp,     g_mlp);

    const int Mtok = BATCH * NTOK;   // 3458
    const int Mpat = BATCH * NPATCH; // 3456
    const int MtokBlocks = (Mtok + GBM - 1) / GBM;  // 28

    // 1) patchify + patch-embed GEMM + cls
    {
        int total = BATCH * NPATCH * PK;
        patchify_kernel<<<(total + 255) / 256, 256>>>(x);
        dim3 grid(EMB / GBN, Mpat / GBM);
        gemm_tc<3><<<grid, 256>>>(patches, conv_w, conv_b, t, Mpat, EMB, PK, pos_embed);
        cls_init_kernel<<<(BATCH * EMB + 255) / 256, 256>>>(cls_token, pos_embed);
    }

    // 2) transformer layers
    for (int i = 0; i < NL; i++) {
        ln_kernel<<<Mtok, 128>>>(t, ln1_w + i * EMB, ln1_b + i * EMB, h);
        {
            dim3 grid(QKVD / GBN, MtokBlocks);
            gemm_tc<0><<<grid, 256>>>(h, qkv_w + (size_t)i * QKVD * EMB,
                                      qkv_b + i * QKVD, qkv, Mtok, QKVD, EMB, nullptr);
        }
        {
            dim3 grid((NTOK + QT - 1) / QT, NH, BATCH);
            attn_flash<<<grid, 256>>>(qkv, attno);
        }
        {
            dim3 grid(EMB / GBN, MtokBlocks);
            gemm_tc<2><<<grid, 256>>>(attno, proj_w + (size_t)i * EMB * EMB,
                                      proj_b + i * EMB, t, Mtok, EMB, EMB, nullptr);
        }
        ln_kernel<<<Mtok, 128>>>(t, ln2_w + i * EMB, ln2_b + i * EMB, h);
        {
            dim3 grid(MLPD / GBN, MtokBlocks);
            gemm_tc<1><<<grid, 256>>>(h, mlp_w1 + (size_t)i * MLPD * EMB,
                                      mlp_b1 + i * MLPD, mlp, Mtok, MLPD, EMB, nullptr);
        }
        {
            dim3 grid(EMB / GBN, MtokBlocks);
            gemm_tc<2><<<grid, 256>>>(mlp, mlp_w2 + (size_t)i * EMB * MLPD,
                                      mlp_b2 + i * EMB, t, Mtok, EMB, MLPD, nullptr);
        }
    }

    // 3) head
    head_kernel<<<BATCH, 128>>>(t, norm_w, norm_b, head_w, head_b, out);
}

// round 13
// speedup vs baseline: 17.7149x; 1.0275x over previous
#include <cuda_runtime.h>
#include <cuda_bf16.h>
#include <math.h>

// ---------------- problem constants ----------------
#define BATCH   2
#define IMG     96
#define PP      8
#define EMB     384
#define NH      8
#define HD      48
#define NL      6
#define MLPD    1536
#define NC      2
#define NPATCH  1728            // (96/8)^3
#define NTOK    1729            // NPATCH + 1
#define PK      512             // P^3 * CIN
#define QKVD    1152            // 3*EMB
#define MTOK    (BATCH * NTOK)  // 3458

// ---------------- device scratch (static, allocation-free) ----------------
// packed bf16x2 hi/lo operand arrays (word = 2 elements)
__device__ unsigned g_patH [BATCH * NPATCH * PK / 2];
__device__ unsigned g_patL [BATCH * NPATCH * PK / 2];
__device__ unsigned g_wconvH[EMB * PK / 2];
__device__ unsigned g_wconvL[EMB * PK / 2];
__device__ unsigned g_wqkvH[NL * QKVD * EMB / 2];
__device__ unsigned g_wqkvL[NL * QKVD * EMB / 2];
__device__ unsigned g_wprojH[NL * EMB * EMB / 2];
__device__ unsigned g_wprojL[NL * EMB * EMB / 2];
__device__ unsigned g_wm1H [NL * MLPD * EMB / 2];
__device__ unsigned g_wm1L [NL * MLPD * EMB / 2];
__device__ unsigned g_wm2H [NL * EMB * MLPD / 2];
__device__ unsigned g_wm2L [NL * EMB * MLPD / 2];
__device__ unsigned g_hH   [MTOK * EMB / 2];
__device__ unsigned g_hL   [MTOK * EMB / 2];
__device__ unsigned g_attnoH[MTOK * EMB / 2];
__device__ unsigned g_attnoL[MTOK * EMB / 2];
__device__ unsigned g_mlpH [MTOK * MLPD / 2];
__device__ unsigned g_mlpL [MTOK * MLPD / 2];
// float buffers
__device__ float g_t  [MTOK * EMB];
__device__ float g_qkv[MTOK * QKVD];

// ---------------- small helpers ----------------
__device__ __forceinline__ void split_pair(float x, float y, unsigned &hi, unsigned &lo) {
    __nv_bfloat16 hx = __float2bfloat16(x);
    __nv_bfloat16 hy = __float2bfloat16(y);
    hi = ((unsigned)__bfloat16_as_ushort(hy) << 16) | (unsigned)__bfloat16_as_ushort(hx);
    float rx = x - __bfloat162float(hx);
    float ry = y - __bfloat162float(hy);
    __nv_bfloat16 lx = __float2bfloat16(rx);
    __nv_bfloat16 ly = __float2bfloat16(ry);
    lo = ((unsigned)__bfloat16_as_ushort(ly) << 16) | (unsigned)__bfloat16_as_ushort(lx);
}

__device__ __forceinline__ void mma_bf16(float c[4], const unsigned a[4],
                                         unsigned b0, unsigned b1) {
    asm volatile(
        "mma.sync.aligned.m16n8k16.row.col.f32.bf16.bf16.f32 "
        "{%0,%1,%2,%3}, {%4,%5,%6,%7}, {%8,%9}, {%0,%1,%2,%3};"
        : "+f"(c[0]), "+f"(c[1]), "+f"(c[2]), "+f"(c[3])
        : "r"(a[0]), "r"(a[1]), "r"(a[2]), "r"(a[3]), "r"(b0), "r"(b1));
}

__device__ __forceinline__ void cp16(void* dst, const void* src, int sz) {
    unsigned d = (unsigned)__cvta_generic_to_shared(dst);
    asm volatile("cp.async.cg.shared.global [%0], [%1], 16, %2;"
                 :: "r"(d), "l"(src), "r"(sz));
}
#define CP_COMMIT() asm volatile("cp.async.commit_group;")
#define CP_WAIT1()  asm volatile("cp.async.wait_group 1;")

// ---------------- generic fp32 -> bf16 hi/lo split (for weights) ----------------
__global__ void split_kernel(const float* __restrict__ src, unsigned* __restrict__ dstH,
                             unsigned* __restrict__ dstL, int npairs) {
    int i = blockIdx.x * blockDim.x + threadIdx.x;
    if (i >= npairs) return;
    float2 v = ((const float2*)src)[i];
    unsigned h, l;
    split_pair(v.x, v.y, h, l);
    dstH[i] = h; dstL[i] = l;
}

// ---------------- patchify: gather + split directly ----------------
__global__ void patchify_kernel(const float* __restrict__ x) {
    int gid = blockIdx.x * blockDim.x + threadIdx.x;
    const int total = BATCH * NPATCH * (PK / 2);
    if (gid >= total) return;
    int pw = gid & (PK / 2 - 1);    // word 0..255
    int r  = gid >> 8;              // patch row
    int e  = pw * 2;                // even element
    int b = r / NPATCH;
    int p = r - b * NPATCH;
    int pz = p / 144;
    int py = (p / 12) % 12;
    int px = p % 12;
    int i = e >> 6;
    int j = (e >> 3) & 7;
    int k = e & 7;                  // even
    size_t src = (size_t)b * IMG * IMG * IMG
               + (size_t)(pz * PP + i) * IMG * IMG
               + (size_t)(py * PP + j) * IMG
               + (px * PP + k);
    float2 v = *(const float2*)&x[src];
    unsigned h, l;
    split_pair(v.x, v.y, h, l);
    g_patH[(size_t)r * (PK / 2) + pw] = h;
    g_patL[(size_t)r * (PK / 2) + pw] = l;
}

__global__ void cls_init_kernel(const float* __restrict__ cls_token,
                                const float* __restrict__ pos_embed) {
    int gid = blockIdx.x * blockDim.x + threadIdx.x;
    if (gid >= BATCH * EMB) return;
    int b = gid / EMB;
    int e = gid - b * EMB;
    g_t[(size_t)b * NTOK * EMB + e] = cls_token[e] + pos_embed[e];
}

// ---------------- 3xBF16 GEMM, pre-split operands, cp.async double buffer ----------------
// C[M,N] = A[M,K] * W[N,K]^T, operands as packed bf16x2 hi/lo words (Kw = K/2 per row).
// EPI: 0 = bias -> float C, 1 = bias+GELU -> split CH/CL, 2 = bias+residual -> float C,
//      3 = patch scatter + pos_embed -> float C
#define GBM 128
#define GBN 128
#define WSTR 12      // 8 data words + 4 pad per row

template<int EPI>
__global__ void __launch_bounds__(256, 2)
gemm_tc(const unsigned* __restrict__ AH, const unsigned* __restrict__ AL,
        const unsigned* __restrict__ WH, const unsigned* __restrict__ WL,
        const float* __restrict__ bias, float* __restrict__ C,
        unsigned* __restrict__ CH, unsigned* __restrict__ CL,
        int M, int N, int K, const float* __restrict__ extra)
{
    __shared__ unsigned sAH[2][GBM * WSTR];
    __shared__ unsigned sAL[2][GBM * WSTR];
    __shared__ unsigned sBH[2][GBN * WSTR];
    __shared__ unsigned sBL[2][GBN * WSTR];

    const int tid  = threadIdx.x;
    const int lane = tid & 31;
    const int warp = tid >> 5;
    const int wm = (warp & 3) * 32;    // warp row offset
    const int wn = (warp >> 2) * 64;   // warp col offset
    const int bm = blockIdx.y * GBM;
    const int bn = blockIdx.x * GBN;
    const int g  = lane >> 2;          // 0..7
    const int tg = lane & 3;           // 0..3

    const int Kw = K >> 1;             // words per full row
    // cp.async mapping: thread -> (row, 16B half-row)
    const int lr = tid >> 1;           // 0..127
    const int lh = (tid & 1) * 4;      // word offset 0 or 4
    const bool aval = (bm + lr) < M;
    const size_t abase = (size_t)(aval ? bm + lr : 0) * Kw + lh;
    const size_t wbase = (size_t)(bn + lr) * Kw + lh;
    const int asz = aval ? 16 : 0;
    const int sOff = lr * WSTR + lh;

    float c[2][8][4];
    #pragma unroll
    for (int i = 0; i < 2; i++)
        #pragma unroll
        for (int j = 0; j < 8; j++)
            #pragma unroll
            for (int v = 0; v < 4; v++) c[i][j][v] = 0.f;

    const int nIter = K >> 4;          // 8 words per k-tile

    // prologue: tile 0 -> stage 0
    cp16(&sAH[0][sOff], AH + abase, asz);
    cp16(&sAL[0][sOff], AL + abase, asz);
    cp16(&sBH[0][sOff], WH + wbase, 16);
    cp16(&sBL[0][sOff], WL + wbase, 16);
    CP_COMMIT();

    for (int it = 0; it < nIter; it++) {
        const int st = it & 1;
        if (it + 1 < nIter) {
            const int kw0 = (it + 1) * 8;
            const int so = (st ^ 1);
            cp16(&sAH[so][sOff], AH + abase + kw0, asz);
            cp16(&sAL[so][sOff], AL + abase + kw0, asz);
            cp16(&sBH[so][sOff], WH + wbase + kw0, 16);
            cp16(&sBL[so][sOff], WL + wbase + kw0, 16);
        }
        CP_COMMIT();
        CP_WAIT1();
        __syncthreads();

        // ---- compute stage st: one m16n8k16 k-step covers the k-tile ----
        const unsigned* aH_s = sAH[st];
        const unsigned* aL_s = sAL[st];
        const unsigned* bH_s = sBH[st];
        const unsigned* bL_s = sBL[st];
        unsigned aH[2][4], aL[2][4];
        #pragma unroll
        for (int i = 0; i < 2; i++) {
            int row = wm + i * 16 + g;
            aH[i][0] = aH_s[row * WSTR + tg];
            aH[i][1] = aH_s[(row + 8) * WSTR + tg];
            aH[i][2] = aH_s[row * WSTR + tg + 4];
            aH[i][3] = aH_s[(row + 8) * WSTR + tg + 4];
            aL[i][0] = aL_s[row * WSTR + tg];
            aL[i][1] = aL_s[(row + 8) * WSTR + tg];
            aL[i][2] = aL_s[row * WSTR + tg + 4];
            aL[i][3] = aL_s[(row + 8) * WSTR + tg + 4];
        }
        #pragma unroll
        for (int j = 0; j < 8; j++) {
            int col = wn + j * 8 + g;
            unsigned bh0 = bH_s[col * WSTR + tg];
            unsigned bh1 = bH_s[col * WSTR + tg + 4];
            unsigned bl0 = bL_s[col * WSTR + tg];
            unsigned bl1 = bL_s[col * WSTR + tg + 4];
            #pragma unroll
            for (int i = 0; i < 2; i++) {
                mma_bf16(c[i][j], aH[i], bh0, bh1);   // hi*hi
                mma_bf16(c[i][j], aH[i], bl0, bl1);   // hi*lo
                mma_bf16(c[i][j], aL[i], bh0, bh1);   // lo*hi
            }
        }
        __syncthreads();
    }

    // ---- epilogue ----
    #pragma unroll
    for (int i = 0; i < 2; i++) {
        #pragma unroll
        for (int half = 0; half < 2; half++) {
            int r = bm + wm + i * 16 + g + half * 8;
            if (r >= M) continue;
            #pragma unroll
            for (int j = 0; j < 8; j++) {
                int col = bn + wn + j * 8 + tg * 2;
                float v0 = c[i][j][half * 2 + 0] + bias[col];
                float v1 = c[i][j][half * 2 + 1] + bias[col + 1];
                if (EPI == 0) {
                    *(float2*)&C[(size_t)r * N + col] = make_float2(v0, v1);
                } else if (EPI == 1) {
                    float g0 = 0.5f * v0 * (1.0f + erff(v0 * 0.70710678118654752f));
                    float g1 = 0.5f * v1 * (1.0f + erff(v1 * 0.70710678118654752f));
                    unsigned hh, ll;
                    split_pair(g0, g1, hh, ll);
                    size_t w = ((size_t)r * N + col) >> 1;
                    CH[w] = hh; CL[w] = ll;
                } else if (EPI == 2) {
                    size_t o = (size_t)r * N + col;
                    float2 old = *(float2*)&C[o];
                    *(float2*)&C[o] = make_float2(old.x + v0, old.y + v1);
                } else { // patch scatter
                    int b = r / NPATCH;
                    int p = r - b * NPATCH;
                    size_t o = ((size_t)b * NTOK + 1 + p) * EMB + col;
                    C[o]     = v0 + extra[(size_t)(1 + p) * EMB + col];
                    C[o + 1] = v1 + extra[(size_t)(1 + p) * EMB + col + 1];
                }
            }
        }
    }
}

// ---------------- LayerNorm -> split bf16 hi/lo output ----------------
__global__ void ln_split_kernel(const float* __restrict__ x, const float* __restrict__ w,
                                const float* __restrict__ bvec,
                                unsigned* __restrict__ yH, unsigned* __restrict__ yL) {
    const int row = blockIdx.x;
    const float* xr = x + (size_t)row * EMB;
    const int tid = threadIdx.x;           // 128
    float s = 0.f, s2 = 0.f;
    #pragma unroll
    for (int e = tid; e < EMB; e += 128) {
        float v = xr[e];
        s += v; s2 += v * v;
    }
    #pragma unroll
    for (int o = 16; o; o >>= 1) {
        s  += __shfl_xor_sync(0xffffffffu, s,  o);
        s2 += __shfl_xor_sync(0xffffffffu, s2, o);
    }
    __shared__ float r1[4], r2[4];
    if ((tid & 31) == 0) { r1[tid >> 5] = s; r2[tid >> 5] = s2; }
    __syncthreads();
    float S  = r1[0] + r1[1] + r1[2] + r1[3];
    float S2 = r2[0] + r2[1] + r2[2] + r2[3];
    float mu = S * (1.0f / EMB);
    float var = S2 * (1.0f / EMB) - mu * mu;
    float rs = rsqrtf(var + 1e-5f);
    #pragma unroll
    for (int p = tid; p < EMB / 2; p += 128) {
        int e = p * 2;
        float v0 = (xr[e]     - mu) * rs * w[e]     + bvec[e];
        float v1 = (xr[e + 1] - mu) * rs * w[e + 1] + bvec[e + 1];
        unsigned hh, ll;
        split_pair(v0, v1, hh, ll);
        yH[(size_t)row * (EMB / 2) + p] = hh;
        yL[(size_t)row * (EMB / 2) + p] = ll;
    }
}

// ---------------- flash attention: block = (64 queries, one (b,h)) ----------------
#define QT 64
#define KT 48
#define AST 52     // padded row stride (floats)

__global__ void __launch_bounds__(256, 1)
attn_flash(const float* __restrict__ qkv,
           unsigned* __restrict__ outH, unsigned* __restrict__ outL) {
    __shared__ float Qs[QT * AST];
    __shared__ float Ks[KT * AST];
    __shared__ float Vs[KT * AST];
    __shared__ float Ps[QT * AST];

    const int tid = threadIdx.x;
    const int h = blockIdx.y, b = blockIdx.z;
    const int qbase = blockIdx.x * QT;
    const int q   = tid >> 2;     // 0..63 query within tile
    const int sub = tid & 3;      // quad lane

    // ---- load Q tile (64 x 48), coalesced float4 ----
    #pragma unroll
    for (int l = 0; l < 3; l++) {
        int idx = tid + 256 * l;          // 0..767
        int row = idx / 12, cc = idx % 12;
        int gq = qbase + row;
        float4 v = (gq < NTOK)
            ? *(const float4*)&qkv[((size_t)(b * NTOK + gq)) * QKVD + h * HD + cc * 4]
            : make_float4(0.f, 0.f, 0.f, 0.f);
        *(float4*)&Qs[row * AST + cc * 4] = v;
    }

    const float scale = 0.14433756729740643f;  // 1/sqrt(48)
    float m = -1e30f, l_sum = 0.f;
    float acc[12];
    #pragma unroll
    for (int j = 0; j < 12; j++) acc[j] = 0.f;

    const int ntiles = (NTOK + KT - 1) / KT;   // 37
    for (int t0 = 0; t0 < ntiles; t0++) {
        const int kbase = t0 * KT;
        __syncthreads();
        #pragma unroll
        for (int l = 0; l < 3; l++) {
            int idx = tid + 256 * l;
            if (idx < KT * 12) {
                int row = idx / 12, cc = idx % 12;
                int gk = kbase + row;
                float4 kv, vv;
                if (gk < NTOK) {
                    size_t base = ((size_t)(b * NTOK + gk)) * QKVD + h * HD;
                    kv = *(const float4*)&qkv[base + EMB + cc * 4];
                    vv = *(const float4*)&qkv[base + 2 * EMB + cc * 4];
                } else {
                    kv = make_float4(0.f, 0.f, 0.f, 0.f);
                    vv = kv;
                }
                *(float4*)&Ks[row * AST + cc * 4] = kv;
                *(float4*)&Vs[row * AST + cc * 4] = vv;
            }
        }
        __syncthreads();

        float s[12];
        #pragma unroll
        for (int kk = 0; kk < 12; kk++) s[kk] = 0.f;
        #pragma unroll
        for (int d4 = 0; d4 < 12; d4++) {
            float4 qd = *(const float4*)&Qs[q * AST + d4 * 4];
            #pragma unroll
            for (int kk = 0; kk < 12; kk++) {
                int k = sub + 4 * kk;
                float4 kd = *(const float4*)&Ks[k * AST + d4 * 4];
                s[kk] += qd.x * kd.x + qd.y * kd.y + qd.z * kd.z + qd.w * kd.w;
            }
        }
        float tmax = -1e30f;
        #pragma unroll
        for (int kk = 0; kk < 12; kk++) {
            int k = sub + 4 * kk;
            s[kk] = (kbase + k < NTOK) ? s[kk] * scale : -1e30f;
            tmax = fmaxf(tmax, s[kk]);
        }
        tmax = fmaxf(tmax, __shfl_xor_sync(0xffffffffu, tmax, 1));
        tmax = fmaxf(tmax, __shfl_xor_sync(0xffffffffu, tmax, 2));
        float mnew = fmaxf(m, tmax);
        float alpha = __expf(m - mnew);
        float psum = 0.f;
        #pragma unroll
        for (int kk = 0; kk < 12; kk++) {
            float p = __expf(s[kk] - mnew);
            psum += p;
            Ps[q * AST + sub + 4 * kk] = p;
        }
        psum += __shfl_xor_sync(0xffffffffu, psum, 1);
        psum += __shfl_xor_sync(0xffffffffu, psum, 2);
        l_sum = l_sum * alpha + psum;
        m = mnew;
        #pragma unroll
        for (int j = 0; j < 12; j++) acc[j] *= alpha;
        __syncthreads();

        const int d0 = sub * 12;
        #pragma unroll 4
        for (int k = 0; k < KT; k++) {
            float p = Ps[q * AST + k];
            float4 v0 = *(const float4*)&Vs[k * AST + d0];
            float4 v1 = *(const float4*)&Vs[k * AST + d0 + 4];
            float4 v2 = *(const float4*)&Vs[k * AST + d0 + 8];
            acc[0] += p * v0.x; acc[1] += p * v0.y; acc[2]  += p * v0.z; acc[3]  += p * v0.w;
            acc[4] += p * v1.x; acc[5] += p * v1.y; acc[6]  += p * v1.z; acc[7]  += p * v1.w;
            acc[8] += p * v2.x; acc[9] += p * v2.y; acc[10] += p * v2.z; acc[11] += p * v2.w;
        }
    }

    int gq = qbase + q;
    if (gq < NTOK) {
        float inv = 1.0f / l_sum;
        size_t w = (((size_t)(b * NTOK + gq)) * EMB + h * HD + sub * 12) >> 1;
        #pragma unroll
        for (int j = 0; j < 6; j++) {
            unsigned hh, ll;
            split_pair(acc[2 * j] * inv, acc[2 * j + 1] * inv, hh, ll);
            outH[w + j] = hh;
            outL[w + j] = ll;
        }
    }
}

// ---------------- final LN(cls) + head ----------------
__global__ void head_kernel(const float* __restrict__ t, const float* __restrict__ nw,
                            const float* __restrict__ nb, const float* __restrict__ hw,
                            const float* __restrict__ hb, float* __restrict__ out) {
    const int b = blockIdx.x;
    const float* xr = t + (size_t)b * NTOK * EMB;
    const int tid = threadIdx.x;
    float s = 0.f, s2 = 0.f;
    for (int e = tid; e < EMB; e += 128) { float v = xr[e]; s += v; s2 += v * v; }
    #pragma unroll
    for (int o = 16; o; o >>= 1) {
        s  += __shfl_xor_sync(0xffffffffu, s,  o);
        s2 += __shfl_xor_sync(0xffffffffu, s2, o);
    }
    __shared__ float r1[4], r2[4], rd0[4], rd1[4];
    if ((tid & 31) == 0) { r1[tid >> 5] = s; r2[tid >> 5] = s2; }
    __syncthreads();
    float S  = r1[0] + r1[1] + r1[2] + r1[3];
    float S2 = r2[0] + r2[1] + r2[2] + r2[3];
    float mu = S * (1.0f / EMB);
    float rs = rsqrtf(S2 * (1.0f / EMB) - mu * mu + 1e-5f);
    float d0 = 0.f, d1 = 0.f;
    for (int e = tid; e < EMB; e += 128) {
        float nv = (xr[e] - mu) * rs * nw[e] + nb[e];
        d0 += nv * hw[e];
        d1 += nv * hw[EMB + e];
    }
    #pragma unroll
    for (int o = 16; o; o >>= 1) {
        d0 += __shfl_xor_sync(0xffffffffu, d0, o);
        d1 += __shfl_xor_sync(0xffffffffu, d1, o);
    }
    if ((tid & 31) == 0) { rd0[tid >> 5] = d0; rd1[tid >> 5] = d1; }
    __syncthreads();
    if (tid == 0) {
        out[b * NC + 0] = rd0[0] + rd0[1] + rd0[2] + rd0[3] + hb[0];
        out[b * NC + 1] = rd1[0] + rd1[1] + rd1[2] + rd1[3] + hb[1];
    }
}

// ---------------- host orchestration ----------------
extern "C" void kernel_launch(void* const* d_in, const int* in_sizes, int n_in,
                              void* d_out, int out_size) {
    const float* x         = (const float*)d_in[0];
    const float* conv_w    = (const float*)d_in[1];
    const float* conv_b    = (const float*)d_in[2];
    const float* cls_token = (const float*)d_in[3];
    const float* pos_embed = (const float*)d_in[4];
    const float* ln1_w     = (const float*)d_in[5];
    const float* ln1_b     = (const float*)d_in[6];
    const float* qkv_w     = (const float*)d_in[7];
    const float* qkv_b     = (const float*)d_in[8];
    const float* proj_w    = (const float*)d_in[9];
    const float* proj_b    = (const float*)d_in[10];
    const float* ln2_w     = (const float*)d_in[11];
    const float* ln2_b     = (const float*)d_in[12];
    const float* mlp_w1    = (const float*)d_in[13];
    const float* mlp_b1    = (const float*)d_in[14];
    const float* mlp_w2    = (const float*)d_in[15];
    const float* mlp_b2    = (const float*)d_in[16];
    const float* norm_w    = (const float*)d_in[17];
    const float* norm_b    = (const float*)d_in[18];
    const float* head_w    = (const float*)d_in[19];
    const float* head_b    = (const float*)d_in[20];
    float* out = (float*)d_out;

    unsigned *patH, *patL, *wconvH, *wconvL, *wqkvH, *wqkvL, *wprojH, *wprojL;
    unsigned *wm1H, *wm1L, *wm2H, *wm2L, *hH, *hL, *attnoH, *attnoL, *mlpH, *mlpL;
    float *t, *qkv;
    cudaGetSymbolAddress((void**)&patH,   g_patH);
    cudaGetSymbolAddress((void**)&patL,   g_patL);
    cudaGetSymbolAddress((void**)&wconvH, g_wconvH);
    cudaGetSymbolAddress((void**)&wconvL, g_wconvL);
    cudaGetSymbolAddress((void**)&wqkvH,  g_wqkvH);
    cudaGetSymbolAddress((void**)&wqkvL,  g_wqkvL);
    cudaGetSymbolAddress((void**)&wprojH, g_wprojH);
    cudaGetSymbolAddress((void**)&wprojL, g_wprojL);
    cudaGetSymbolAddress((void**)&wm1H,   g_wm1H);
    cudaGetSymbolAddress((void**)&wm1L,   g_wm1L);
    cudaGetSymbolAddress((void**)&wm2H,   g_wm2H);
    cudaGetSymbolAddress((void**)&wm2L,   g_wm2L);
    cudaGetSymbolAddress((void**)&hH,     g_hH);
    cudaGetSymbolAddress((void**)&hL,     g_hL);
    cudaGetSymbolAddress((void**)&attnoH, g_attnoH);
    cudaGetSymbolAddress((void**)&attnoL, g_attnoL);
    cudaGetSymbolAddress((void**)&mlpH,   g_mlpH);
    cudaGetSymbolAddress((void**)&mlpL,   g_mlpL);
    cudaGetSymbolAddress((void**)&t,      g_t);
    cudaGetSymbolAddress((void**)&qkv,    g_qkv);

    const int Mtok = MTOK;           // 3458
    const int Mpat = BATCH * NPATCH; // 3456
    const int MtokBlocks = (Mtok + GBM - 1) / GBM;  // 28

    // 0) weight splits (cheap elementwise)
    {
        int np;
        np = EMB * PK / 2;             split_kernel<<<(np + 255) / 256, 256>>>(conv_w, wconvH, wconvL, np);
        np = NL * QKVD * EMB / 2;      split_kernel<<<(np + 255) / 256, 256>>>(qkv_w,  wqkvH,  wqkvL,  np);
        np = NL * EMB * EMB / 2;       split_kernel<<<(np + 255) / 256, 256>>>(proj_w, wprojH, wprojL, np);
        np = NL * MLPD * EMB / 2;      split_kernel<<<(np + 255) / 256, 256>>>(mlp_w1, wm1H,   wm1L,   np);
        np = NL * EMB * MLPD / 2;      split_kernel<<<(np + 255) / 256, 256>>>(mlp_w2, wm2H,   wm2L,   np);
    }

    // 1) patchify(+split) + patch-embed GEMM + cls
    {
        int total = BATCH * NPATCH * (PK / 2);
        patchify_kernel<<<(total + 255) / 256, 256>>>(x);
        dim3 grid(EMB / GBN, Mpat / GBM);
        gemm_tc<3><<<grid, 256>>>(patH, patL, wconvH, wconvL, conv_b, t, nullptr, nullptr,
                                  Mpat, EMB, PK, pos_embed);
        cls_init_kernel<<<(BATCH * EMB + 255) / 256, 256>>>(cls_token, pos_embed);
    }

    // 2) transformer layers
    for (int i = 0; i < NL; i++) {
        ln_split_kernel<<<Mtok, 128>>>(t, ln1_w + i * EMB, ln1_b + i * EMB, hH, hL);
        {
            dim3 grid(QKVD / GBN, MtokBlocks);
            gemm_tc<0><<<grid, 256>>>(hH, hL,
                                      wqkvH + (size_t)i * QKVD * EMB / 2,
                                      wqkvL + (size_t)i * QKVD * EMB / 2,
                                      qkv_b + i * QKVD, qkv, nullptr, nullptr,
                                      Mtok, QKVD, EMB, nullptr);
        }
        {
            dim3 grid((NTOK + QT - 1) / QT, NH, BATCH);
            attn_flash<<<grid, 256>>>(qkv, attnoH, attnoL);
        }
        {
            dim3 grid(EMB / GBN, MtokBlocks);
            gemm_tc<2><<<grid, 256>>>(attnoH, attnoL,
                                      wprojH + (size_t)i * EMB * EMB / 2,
                                      wprojL + (size_t)i * EMB * EMB / 2,
                                      proj_b + i * EMB, t, nullptr, nullptr,
                                      Mtok, EMB, EMB, nullptr);
        }
        ln_split_kernel<<<Mtok, 128>>>(t, ln2_w + i * EMB, ln2_b + i * EMB, hH, hL);
        {
            dim3 grid(MLPD / GBN, MtokBlocks);
            gemm_tc<1><<<grid, 256>>>(hH, hL,
                                      wm1H + (size_t)i * MLPD * EMB / 2,
                                      wm1L + (size_t)i * MLPD * EMB / 2,
                                      mlp_b1 + i * MLPD, nullptr, mlpH, mlpL,
                                      Mtok, MLPD, EMB, nullptr);
        }
        {
            dim3 grid(EMB / GBN, MtokBlocks);
            gemm_tc<2><<<grid, 256>>>(mlpH, mlpL,
                                      wm2H + (size_t)i * EMB * MLPD / 2,
                                      wm2L + (size_t)i * EMB * MLPD / 2,
                                      mlp_b2 + i * EMB, t, nullptr, nullptr,
                                      Mtok, EMB, MLPD, nullptr);
        }
    }

    // 3) head
    head_kernel<<<BATCH, 128>>>(t, norm_w, norm_b, head_w, head_b, out);
}

// round 14
// speedup vs baseline: 35.2591x; 1.9904x over previous
#include <cuda_runtime.h>
#include <cuda_bf16.h>
#include <math.h>

// ---------------- problem constants ----------------
#define BATCH   2
#define IMG     96
#define PP      8
#define EMB     384
#define NH      8
#define HD      48
#define NL      6
#define MLPD    1536
#define NC      2
#define NPATCH  1728            // (96/8)^3
#define NTOK    1729            // NPATCH + 1
#define PK      512             // P^3 * CIN
#define QKVD    1152            // 3*EMB
#define MTOK    (BATCH * NTOK)  // 3458

// ---------------- device scratch (static, allocation-free) ----------------
__device__ unsigned g_patH [BATCH * NPATCH * PK / 2];
__device__ unsigned g_patL [BATCH * NPATCH * PK / 2];
__device__ unsigned g_wconvH[EMB * PK / 2];
__device__ unsigned g_wconvL[EMB * PK / 2];
__device__ unsigned g_wqkvH[NL * QKVD * EMB / 2];
__device__ unsigned g_wqkvL[NL * QKVD * EMB / 2];
__device__ unsigned g_wprojH[NL * EMB * EMB / 2];
__device__ unsigned g_wprojL[NL * EMB * EMB / 2];
__device__ unsigned g_wm1H [NL * MLPD * EMB / 2];
__device__ unsigned g_wm1L [NL * MLPD * EMB / 2];
__device__ unsigned g_wm2H [NL * EMB * MLPD / 2];
__device__ unsigned g_wm2L [NL * EMB * MLPD / 2];
__device__ unsigned g_hH   [MTOK * EMB / 2];
__device__ unsigned g_hL   [MTOK * EMB / 2];
__device__ unsigned g_attnoH[MTOK * EMB / 2];
__device__ unsigned g_attnoL[MTOK * EMB / 2];
__device__ unsigned g_mlpH [MTOK * MLPD / 2];
__device__ unsigned g_mlpL [MTOK * MLPD / 2];
__device__ float g_t  [MTOK * EMB];
__device__ float g_qkv[MTOK * QKVD];

// ---------------- small helpers ----------------
__device__ __forceinline__ void split_pair(float x, float y, unsigned &hi, unsigned &lo) {
    __nv_bfloat16 hx = __float2bfloat16(x);
    __nv_bfloat16 hy = __float2bfloat16(y);
    hi = ((unsigned)__bfloat16_as_ushort(hy) << 16) | (unsigned)__bfloat16_as_ushort(hx);
    float rx = x - __bfloat162float(hx);
    float ry = y - __bfloat162float(hy);
    __nv_bfloat16 lx = __float2bfloat16(rx);
    __nv_bfloat16 ly = __float2bfloat16(ry);
    lo = ((unsigned)__bfloat16_as_ushort(ly) << 16) | (unsigned)__bfloat16_as_ushort(lx);
}

__device__ __forceinline__ void mma_bf16(float c[4], const unsigned a[4],
                                         unsigned b0, unsigned b1) {
    asm volatile(
        "mma.sync.aligned.m16n8k16.row.col.f32.bf16.bf16.f32 "
        "{%0,%1,%2,%3}, {%4,%5,%6,%7}, {%8,%9}, {%0,%1,%2,%3};"
        : "+f"(c[0]), "+f"(c[1]), "+f"(c[2]), "+f"(c[3])
        : "r"(a[0]), "r"(a[1]), "r"(a[2]), "r"(a[3]), "r"(b0), "r"(b1));
}

__device__ __forceinline__ void cp16(void* dst, const void* src, int sz) {
    unsigned d = (unsigned)__cvta_generic_to_shared(dst);
    asm volatile("cp.async.cg.shared.global [%0], [%1], 16, %2;"
                 :: "r"(d), "l"(src), "r"(sz));
}
#define CP_COMMIT() asm volatile("cp.async.commit_group;")
#define CP_WAIT1()  asm volatile("cp.async.wait_group 1;")

// ---------------- generic fp32 -> bf16 hi/lo split (for weights) ----------------
__global__ void split_kernel(const float* __restrict__ src, unsigned* __restrict__ dstH,
                             unsigned* __restrict__ dstL, int npairs) {
    int i = blockIdx.x * blockDim.x + threadIdx.x;
    if (i >= npairs) return;
    float2 v = ((const float2*)src)[i];
    unsigned h, l;
    split_pair(v.x, v.y, h, l);
    dstH[i] = h; dstL[i] = l;
}

// ---------------- patchify: gather + split directly ----------------
__global__ void patchify_kernel(const float* __restrict__ x) {
    int gid = blockIdx.x * blockDim.x + threadIdx.x;
    const int total = BATCH * NPATCH * (PK / 2);
    if (gid >= total) return;
    int pw = gid & (PK / 2 - 1);
    int r  = gid >> 8;
    int e  = pw * 2;
    int b = r / NPATCH;
    int p = r - b * NPATCH;
    int pz = p / 144;
    int py = (p / 12) % 12;
    int px = p % 12;
    int i = e >> 6;
    int j = (e >> 3) & 7;
    int k = e & 7;
    size_t src = (size_t)b * IMG * IMG * IMG
               + (size_t)(pz * PP + i) * IMG * IMG
               + (size_t)(py * PP + j) * IMG
               + (px * PP + k);
    float2 v = *(const float2*)&x[src];
    unsigned h, l;
    split_pair(v.x, v.y, h, l);
    g_patH[(size_t)r * (PK / 2) + pw] = h;
    g_patL[(size_t)r * (PK / 2) + pw] = l;
}

__global__ void cls_init_kernel(const float* __restrict__ cls_token,
                                const float* __restrict__ pos_embed) {
    int gid = blockIdx.x * blockDim.x + threadIdx.x;
    if (gid >= BATCH * EMB) return;
    int b = gid / EMB;
    int e = gid - b * EMB;
    g_t[(size_t)b * NTOK * EMB + e] = cls_token[e] + pos_embed[e];
}

// ---------------- 3xBF16 GEMM, pre-split operands, cp.async double buffer ----------------
#define GBM 128
#define GBN 128
#define WSTR 12

template<int EPI>
__global__ void __launch_bounds__(256, 2)
gemm_tc(const unsigned* __restrict__ AH, const unsigned* __restrict__ AL,
        const unsigned* __restrict__ WH, const unsigned* __restrict__ WL,
        const float* __restrict__ bias, float* __restrict__ C,
        unsigned* __restrict__ CH, unsigned* __restrict__ CL,
        int M, int N, int K, const float* __restrict__ extra)
{
    __shared__ unsigned sAH[2][GBM * WSTR];
    __shared__ unsigned sAL[2][GBM * WSTR];
    __shared__ unsigned sBH[2][GBN * WSTR];
    __shared__ unsigned sBL[2][GBN * WSTR];

    const int tid  = threadIdx.x;
    const int lane = tid & 31;
    const int warp = tid >> 5;
    const int wm = (warp & 3) * 32;
    const int wn = (warp >> 2) * 64;
    const int bm = blockIdx.y * GBM;
    const int bn = blockIdx.x * GBN;
    const int g  = lane >> 2;
    const int tg = lane & 3;

    const int Kw = K >> 1;
    const int lr = tid >> 1;
    const int lh = (tid & 1) * 4;
    const bool aval = (bm + lr) < M;
    const size_t abase = (size_t)(aval ? bm + lr : 0) * Kw + lh;
    const size_t wbase = (size_t)(bn + lr) * Kw + lh;
    const int asz = aval ? 16 : 0;
    const int sOff = lr * WSTR + lh;

    float c[2][8][4];
    #pragma unroll
    for (int i = 0; i < 2; i++)
        #pragma unroll
        for (int j = 0; j < 8; j++)
            #pragma unroll
            for (int v = 0; v < 4; v++) c[i][j][v] = 0.f;

    const int nIter = K >> 4;

    cp16(&sAH[0][sOff], AH + abase, asz);
    cp16(&sAL[0][sOff], AL + abase, asz);
    cp16(&sBH[0][sOff], WH + wbase, 16);
    cp16(&sBL[0][sOff], WL + wbase, 16);
    CP_COMMIT();

    for (int it = 0; it < nIter; it++) {
        const int st = it & 1;
        if (it + 1 < nIter) {
            const int kw0 = (it + 1) * 8;
            const int so = (st ^ 1);
            cp16(&sAH[so][sOff], AH + abase + kw0, asz);
            cp16(&sAL[so][sOff], AL + abase + kw0, asz);
            cp16(&sBH[so][sOff], WH + wbase + kw0, 16);
            cp16(&sBL[so][sOff], WL + wbase + kw0, 16);
        }
        CP_COMMIT();
        CP_WAIT1();
        __syncthreads();

        const unsigned* aH_s = sAH[st];
        const unsigned* aL_s = sAL[st];
        const unsigned* bH_s = sBH[st];
        const unsigned* bL_s = sBL[st];
        unsigned aH[2][4], aL[2][4];
        #pragma unroll
        for (int i = 0; i < 2; i++) {
            int row = wm + i * 16 + g;
            aH[i][0] = aH_s[row * WSTR + tg];
            aH[i][1] = aH_s[(row + 8) * WSTR + tg];
            aH[i][2] = aH_s[row * WSTR + tg + 4];
            aH[i][3] = aH_s[(row + 8) * WSTR + tg + 4];
            aL[i][0] = aL_s[row * WSTR + tg];
            aL[i][1] = aL_s[(row + 8) * WSTR + tg];
            aL[i][2] = aL_s[row * WSTR + tg + 4];
            aL[i][3] = aL_s[(row + 8) * WSTR + tg + 4];
        }
        #pragma unroll
        for (int j = 0; j < 8; j++) {
            int col = wn + j * 8 + g;
            unsigned bh0 = bH_s[col * WSTR + tg];
            unsigned bh1 = bH_s[col * WSTR + tg + 4];
            unsigned bl0 = bL_s[col * WSTR + tg];
            unsigned bl1 = bL_s[col * WSTR + tg + 4];
            #pragma unroll
            for (int i = 0; i < 2; i++) {
                mma_bf16(c[i][j], aH[i], bh0, bh1);
                mma_bf16(c[i][j], aH[i], bl0, bl1);
                mma_bf16(c[i][j], aL[i], bh0, bh1);
            }
        }
        __syncthreads();
    }

    #pragma unroll
    for (int i = 0; i < 2; i++) {
        #pragma unroll
        for (int half = 0; half < 2; half++) {
            int r = bm + wm + i * 16 + g + half * 8;
            if (r >= M) continue;
            #pragma unroll
            for (int j = 0; j < 8; j++) {
                int col = bn + wn + j * 8 + tg * 2;
                float v0 = c[i][j][half * 2 + 0] + bias[col];
                float v1 = c[i][j][half * 2 + 1] + bias[col + 1];
                if (EPI == 0) {
                    *(float2*)&C[(size_t)r * N + col] = make_float2(v0, v1);
                } else if (EPI == 1) {
                    float g0 = 0.5f * v0 * (1.0f + erff(v0 * 0.70710678118654752f));
                    float g1 = 0.5f * v1 * (1.0f + erff(v1 * 0.70710678118654752f));
                    unsigned hh, ll;
                    split_pair(g0, g1, hh, ll);
                    size_t w = ((size_t)r * N + col) >> 1;
                    CH[w] = hh; CL[w] = ll;
                } else if (EPI == 2) {
                    size_t o = (size_t)r * N + col;
                    float2 old = *(float2*)&C[o];
                    *(float2*)&C[o] = make_float2(old.x + v0, old.y + v1);
                } else {
                    int b = r / NPATCH;
                    int p = r - b * NPATCH;
                    size_t o = ((size_t)b * NTOK + 1 + p) * EMB + col;
                    C[o]     = v0 + extra[(size_t)(1 + p) * EMB + col];
                    C[o + 1] = v1 + extra[(size_t)(1 + p) * EMB + col + 1];
                }
            }
        }
    }
}

// ---------------- LayerNorm -> split bf16 hi/lo output ----------------
__global__ void ln_split_kernel(const float* __restrict__ x, const float* __restrict__ w,
                                const float* __restrict__ bvec,
                                unsigned* __restrict__ yH, unsigned* __restrict__ yL) {
    const int row = blockIdx.x;
    const float* xr = x + (size_t)row * EMB;
    const int tid = threadIdx.x;
    float s = 0.f, s2 = 0.f;
    #pragma unroll
    for (int e = tid; e < EMB; e += 128) {
        float v = xr[e];
        s += v; s2 += v * v;
    }
    #pragma unroll
    for (int o = 16; o; o >>= 1) {
        s  += __shfl_xor_sync(0xffffffffu, s,  o);
        s2 += __shfl_xor_sync(0xffffffffu, s2, o);
    }
    __shared__ float r1[4], r2[4];
    if ((tid & 31) == 0) { r1[tid >> 5] = s; r2[tid >> 5] = s2; }
    __syncthreads();
    float S  = r1[0] + r1[1] + r1[2] + r1[3];
    float S2 = r2[0] + r2[1] + r2[2] + r2[3];
    float mu = S * (1.0f / EMB);
    float var = S2 * (1.0f / EMB) - mu * mu;
    float rs = rsqrtf(var + 1e-5f);
    #pragma unroll
    for (int p = tid; p < EMB / 2; p += 128) {
        int e = p * 2;
        float v0 = (xr[e]     - mu) * rs * w[e]     + bvec[e];
        float v1 = (xr[e + 1] - mu) * rs * w[e + 1] + bvec[e + 1];
        unsigned hh, ll;
        split_pair(v0, v1, hh, ll);
        yH[(size_t)row * (EMB / 2) + p] = hh;
        yL[(size_t)row * (EMB / 2) + p] = ll;
    }
}

// ---------------- tensor-core flash attention (3xBF16 split) ----------------
// Block: 8 warps, each warp owns 16 queries (AQT=128 q/block), one (b,h).
// Q fragments persistent in registers; K,V tiles (48 keys) staged in SMEM.
#define AQT 128
#define AKT 48
#define KSTR 28     // words per K row (24 data + 4 pad) -> conflict-free fragments
#define VSTR 28     // words per Vt row (24 data = 48 keys)

__global__ void __launch_bounds__(256, 1)
attn_mma(const float* __restrict__ qkv,
         unsigned* __restrict__ outH, unsigned* __restrict__ outL) {
    __shared__ unsigned ksH[AKT * KSTR], ksL[AKT * KSTR];   // 10.5 KB
    __shared__ unsigned vsH[HD * VSTR],  vsL[HD * VSTR];    // 10.5 KB

    const int tid  = threadIdx.x;
    const int lane = tid & 31;
    const int warp = tid >> 5;
    const int g  = lane >> 2;
    const int tg = lane & 3;
    const int h = blockIdx.y, b = blockIdx.z;
    const int qbase = blockIdx.x * AQT;
    const float scale = 0.14433756729740643f;   // 1/sqrt(48)

    // ---- persistent Q fragments (pre-scaled, hi/lo split) ----
    unsigned qfH[3][4], qfL[3][4];
    {
        const int r0 = qbase + 16 * warp + g;
        #pragma unroll
        for (int ks = 0; ks < 3; ks++) {
            #pragma unroll
            for (int sl = 0; sl < 4; sl++) {
                int r = r0 + (sl & 1) * 8;
                int cc = 16 * ks + 2 * tg + (sl >> 1) * 8;
                float2 v = make_float2(0.f, 0.f);
                if (r < NTOK)
                    v = *(const float2*)&qkv[((size_t)(b * NTOK + r)) * QKVD + h * HD + cc];
                split_pair(v.x * scale, v.y * scale, qfH[ks][sl], qfL[ks][sl]);
            }
        }
    }

    float acc[6][4];
    #pragma unroll
    for (int n = 0; n < 6; n++)
        #pragma unroll
        for (int v = 0; v < 4; v++) acc[n][v] = 0.f;
    float m0 = -1e30f, m1 = -1e30f, l0 = 0.f, l1 = 0.f;

    const int ntiles = (NTOK + AKT - 1) / AKT;   // 37
    for (int t0 = 0; t0 < ntiles; t0++) {
        const int kbase = t0 * AKT;
        __syncthreads();
        // ---- load K (split) and V (split + transpose) ----
        #pragma unroll
        for (int lp = 0; lp < 3; lp++) {
            int idx = tid + 256 * lp;
            if (idx < AKT * 12) {
                int row = idx / 12, c4 = idx % 12;
                int gk = kbase + row;
                float4 kv = make_float4(0.f, 0.f, 0.f, 0.f), vv = kv;
                if (gk < NTOK) {
                    size_t base = ((size_t)(b * NTOK + gk)) * QKVD + h * HD;
                    kv = *(const float4*)&qkv[base + EMB + c4 * 4];
                    vv = *(const float4*)&qkv[base + 2 * EMB + c4 * 4];
                }
                unsigned hh, ll;
                split_pair(kv.x, kv.y, hh, ll);
                ksH[row * KSTR + 2 * c4] = hh; ksL[row * KSTR + 2 * c4] = ll;
                split_pair(kv.z, kv.w, hh, ll);
                ksH[row * KSTR + 2 * c4 + 1] = hh; ksL[row * KSTR + 2 * c4 + 1] = ll;
                __nv_bfloat16* vbh = (__nv_bfloat16*)vsH;
                __nv_bfloat16* vbl = (__nv_bfloat16*)vsL;
                float vals[4] = {vv.x, vv.y, vv.z, vv.w};
                #pragma unroll
                for (int cc = 0; cc < 4; cc++) {
                    int d = 4 * c4 + cc;
                    __nv_bfloat16 hb = __float2bfloat16(vals[cc]);
                    vbh[d * (VSTR * 2) + row] = hb;
                    vbl[d * (VSTR * 2) + row] = __float2bfloat16(vals[cc] - __bfloat162float(hb));
                }
            }
        }
        __syncthreads();

        // ---- QK scores: 6 n-tiles x 3 k-steps x 3 split terms ----
        float s[6][4];
        #pragma unroll
        for (int j = 0; j < 6; j++)
            #pragma unroll
            for (int v = 0; v < 4; v++) s[j][v] = 0.f;
        #pragma unroll
        for (int j = 0; j < 6; j++) {
            #pragma unroll
            for (int ks = 0; ks < 3; ks++) {
                int o = (8 * j + g) * KSTR + 8 * ks + tg;
                unsigned bh0 = ksH[o], bh1 = ksH[o + 4];
                unsigned bl0 = ksL[o], bl1 = ksL[o + 4];
                mma_bf16(s[j], qfH[ks], bh0, bh1);
                mma_bf16(s[j], qfH[ks], bl0, bl1);
                mma_bf16(s[j], qfL[ks], bh0, bh1);
            }
        }
        // mask (last tile only)
        if (kbase + AKT > NTOK) {
            #pragma unroll
            for (int j = 0; j < 6; j++) {
                int k0 = kbase + 8 * j + 2 * tg;
                if (k0     >= NTOK) { s[j][0] = -1e30f; s[j][2] = -1e30f; }
                if (k0 + 1 >= NTOK) { s[j][1] = -1e30f; s[j][3] = -1e30f; }
            }
        }
        // ---- online softmax (rows g and g+8 separately) ----
        float mx0 = -1e30f, mx1 = -1e30f;
        #pragma unroll
        for (int j = 0; j < 6; j++) {
            mx0 = fmaxf(mx0, fmaxf(s[j][0], s[j][1]));
            mx1 = fmaxf(mx1, fmaxf(s[j][2], s[j][3]));
        }
        mx0 = fmaxf(mx0, __shfl_xor_sync(0xffffffffu, mx0, 1));
        mx0 = fmaxf(mx0, __shfl_xor_sync(0xffffffffu, mx0, 2));
        mx1 = fmaxf(mx1, __shfl_xor_sync(0xffffffffu, mx1, 1));
        mx1 = fmaxf(mx1, __shfl_xor_sync(0xffffffffu, mx1, 2));
        float mn0 = fmaxf(m0, mx0), mn1 = fmaxf(m1, mx1);
        float a0 = __expf(m0 - mn0), a1 = __expf(m1 - mn1);
        unsigned ph0[6], pl0[6], ph1[6], pl1[6];
        float ps0 = 0.f, ps1 = 0.f;
        #pragma unroll
        for (int j = 0; j < 6; j++) {
            float p0 = __expf(s[j][0] - mn0);
            float p1 = __expf(s[j][1] - mn0);
            float p2 = __expf(s[j][2] - mn1);
            float p3 = __expf(s[j][3] - mn1);
            ps0 += p0 + p1; ps1 += p2 + p3;
            split_pair(p0, p1, ph0[j], pl0[j]);
            split_pair(p2, p3, ph1[j], pl1[j]);
        }
        ps0 += __shfl_xor_sync(0xffffffffu, ps0, 1);
        ps0 += __shfl_xor_sync(0xffffffffu, ps0, 2);
        ps1 += __shfl_xor_sync(0xffffffffu, ps1, 1);
        ps1 += __shfl_xor_sync(0xffffffffu, ps1, 2);
        l0 = l0 * a0 + ps0;
        l1 = l1 * a1 + ps1;
        m0 = mn0; m1 = mn1;
        #pragma unroll
        for (int n = 0; n < 6; n++) {
            acc[n][0] *= a0; acc[n][1] *= a0;
            acc[n][2] *= a1; acc[n][3] *= a1;
        }
        // ---- PV: P fragments from packed registers, V from transposed SMEM ----
        #pragma unroll
        for (int ks = 0; ks < 3; ks++) {
            unsigned aPh[4] = { ph0[2 * ks], ph1[2 * ks], ph0[2 * ks + 1], ph1[2 * ks + 1] };
            unsigned aPl[4] = { pl0[2 * ks], pl1[2 * ks], pl0[2 * ks + 1], pl1[2 * ks + 1] };
            #pragma unroll
            for (int n = 0; n < 6; n++) {
                int o = (8 * n + g) * VSTR + 8 * ks + tg;
                unsigned bh0 = vsH[o], bh1 = vsH[o + 4];
                unsigned bl0 = vsL[o], bl1 = vsL[o + 4];
                mma_bf16(acc[n], aPh, bh0, bh1);
                mma_bf16(acc[n], aPh, bl0, bl1);
                mma_bf16(acc[n], aPl, bh0, bh1);
            }
        }
    }

    // ---- epilogue: normalize + split-store ----
    const int r0 = qbase + 16 * warp + g;
    const int r1 = r0 + 8;
    float inv0 = 1.0f / l0, inv1 = 1.0f / l1;
    if (r0 < NTOK) {
        size_t wb = (size_t)(b * NTOK + r0) * (EMB / 2) + 24 * h + tg;
        #pragma unroll
        for (int n = 0; n < 6; n++) {
            unsigned hh, ll;
            split_pair(acc[n][0] * inv0, acc[n][1] * inv0, hh, ll);
            outH[wb + 4 * n] = hh; outL[wb + 4 * n] = ll;
        }
    }
    if (r1 < NTOK) {
        size_t wb = (size_t)(b * NTOK + r1) * (EMB / 2) + 24 * h + tg;
        #pragma unroll
        for (int n = 0; n < 6; n++) {
            unsigned hh, ll;
            split_pair(acc[n][2] * inv1, acc[n][3] * inv1, hh, ll);
            outH[wb + 4 * n] = hh; outL[wb + 4 * n] = ll;
        }
    }
}

// ---------------- final LN(cls) + head ----------------
__global__ void head_kernel(const float* __restrict__ t, const float* __restrict__ nw,
                            const float* __restrict__ nb, const float* __restrict__ hw,
                            const float* __restrict__ hb, float* __restrict__ out) {
    const int b = blockIdx.x;
    const float* xr = t + (size_t)b * NTOK * EMB;
    const int tid = threadIdx.x;
    float s = 0.f, s2 = 0.f;
    for (int e = tid; e < EMB; e += 128) { float v = xr[e]; s += v; s2 += v * v; }
    #pragma unroll
    for (int o = 16; o; o >>= 1) {
        s  += __shfl_xor_sync(0xffffffffu, s,  o);
        s2 += __shfl_xor_sync(0xffffffffu, s2, o);
    }
    __shared__ float r1[4], r2[4], rd0[4], rd1[4];
    if ((tid & 31) == 0) { r1[tid >> 5] = s; r2[tid >> 5] = s2; }
    __syncthreads();
    float S  = r1[0] + r1[1] + r1[2] + r1[3];
    float S2 = r2[0] + r2[1] + r2[2] + r2[3];
    float mu = S * (1.0f / EMB);
    float rs = rsqrtf(S2 * (1.0f / EMB) - mu * mu + 1e-5f);
    float d0 = 0.f, d1 = 0.f;
    for (int e = tid; e < EMB; e += 128) {
        float nv = (xr[e] - mu) * rs * nw[e] + nb[e];
        d0 += nv * hw[e];
        d1 += nv * hw[EMB + e];
    }
    #pragma unroll
    for (int o = 16; o; o >>= 1) {
        d0 += __shfl_xor_sync(0xffffffffu, d0, o);
        d1 += __shfl_xor_sync(0xffffffffu, d1, o);
    }
    if ((tid & 31) == 0) { rd0[tid >> 5] = d0; rd1[tid >> 5] = d1; }
    __syncthreads();
    if (tid == 0) {
        out[b * NC + 0] = rd0[0] + rd0[1] + rd0[2] + rd0[3] + hb[0];
        out[b * NC + 1] = rd1[0] + rd1[1] + rd1[2] + rd1[3] + hb[1];
    }
}

// ---------------- host orchestration ----------------
extern "C" void kernel_launch(void* const* d_in, const int* in_sizes, int n_in,
                              void* d_out, int out_size) {
    const float* x         = (const float*)d_in[0];
    const float* conv_w    = (const float*)d_in[1];
    const float* conv_b    = (const float*)d_in[2];
    const float* cls_token = (const float*)d_in[3];
    const float* pos_embed = (const float*)d_in[4];
    const float* ln1_w     = (const float*)d_in[5];
    const float* ln1_b     = (const float*)d_in[6];
    const float* qkv_w     = (const float*)d_in[7];
    const float* qkv_b     = (const float*)d_in[8];
    const float* proj_w    = (const float*)d_in[9];
    const float* proj_b    = (const float*)d_in[10];
    const float* ln2_w     = (const float*)d_in[11];
    const float* ln2_b     = (const float*)d_in[12];
    const float* mlp_w1    = (const float*)d_in[13];
    const float* mlp_b1    = (const float*)d_in[14];
    const float* mlp_w2    = (const float*)d_in[15];
    const float* mlp_b2    = (const float*)d_in[16];
    const float* norm_w    = (const float*)d_in[17];
    const float* norm_b    = (const float*)d_in[18];
    const float* head_w    = (const float*)d_in[19];
    const float* head_b    = (const float*)d_in[20];
    float* out = (float*)d_out;

    unsigned *patH, *patL, *wconvH, *wconvL, *wqkvH, *wqkvL, *wprojH, *wprojL;
    unsigned *wm1H, *wm1L, *wm2H, *wm2L, *hH, *hL, *attnoH, *attnoL, *mlpH, *mlpL;
    float *t, *qkv;
    cudaGetSymbolAddress((void**)&patH,   g_patH);
    cudaGetSymbolAddress((void**)&patL,   g_patL);
    cudaGetSymbolAddress((void**)&wconvH, g_wconvH);
    cudaGetSymbolAddress((void**)&wconvL, g_wconvL);
    cudaGetSymbolAddress((void**)&wqkvH,  g_wqkvH);
    cudaGetSymbolAddress((void**)&wqkvL,  g_wqkvL);
    cudaGetSymbolAddress((void**)&wprojH, g_wprojH);
    cudaGetSymbolAddress((void**)&wprojL, g_wprojL);
    cudaGetSymbolAddress((void**)&wm1H,   g_wm1H);
    cudaGetSymbolAddress((void**)&wm1L,   g_wm1L);
    cudaGetSymbolAddress((void**)&wm2H,   g_wm2H);
    cudaGetSymbolAddress((void**)&wm2L,   g_wm2L);
    cudaGetSymbolAddress((void**)&hH,     g_hH);
    cudaGetSymbolAddress((void**)&hL,     g_hL);
    cudaGetSymbolAddress((void**)&attnoH, g_attnoH);
    cudaGetSymbolAddress((void**)&attnoL, g_attnoL);
    cudaGetSymbolAddress((void**)&mlpH,   g_mlpH);
    cudaGetSymbolAddress((void**)&mlpL,   g_mlpL);
    cudaGetSymbolAddress((void**)&t,      g_t);
    cudaGetSymbolAddress((void**)&qkv,    g_qkv);

    const int Mtok = MTOK;
    const int Mpat = BATCH * NPATCH;
    const int MtokBlocks = (Mtok + GBM - 1) / GBM;

    // 0) weight splits
    {
        int np;
        np = EMB * PK / 2;             split_kernel<<<(np + 255) / 256, 256>>>(conv_w, wconvH, wconvL, np);
        np = NL * QKVD * EMB / 2;      split_kernel<<<(np + 255) / 256, 256>>>(qkv_w,  wqkvH,  wqkvL,  np);
        np = NL * EMB * EMB / 2;       split_kernel<<<(np + 255) / 256, 256>>>(proj_w, wprojH, wprojL, np);
        np = NL * MLPD * EMB / 2;      split_kernel<<<(np + 255) / 256, 256>>>(mlp_w1, wm1H,   wm1L,   np);
        np = NL * EMB * MLPD / 2;      split_kernel<<<(np + 255) / 256, 256>>>(mlp_w2, wm2H,   wm2L,   np);
    }

    // 1) patchify(+split) + patch-embed GEMM + cls
    {
        int total = BATCH * NPATCH * (PK / 2);
        patchify_kernel<<<(total + 255) / 256, 256>>>(x);
        dim3 grid(EMB / GBN, Mpat / GBM);
        gemm_tc<3><<<grid, 256>>>(patH, patL, wconvH, wconvL, conv_b, t, nullptr, nullptr,
                                  Mpat, EMB, PK, pos_embed);
        cls_init_kernel<<<(BATCH * EMB + 255) / 256, 256>>>(cls_token, pos_embed);
    }

    // 2) transformer layers
    for (int i = 0; i < NL; i++) {
        ln_split_kernel<<<Mtok, 128>>>(t, ln1_w + i * EMB, ln1_b + i * EMB, hH, hL);
        {
            dim3 grid(QKVD / GBN, MtokBlocks);
            gemm_tc<0><<<grid, 256>>>(hH, hL,
                                      wqkvH + (size_t)i * QKVD * EMB / 2,
                                      wqkvL + (size_t)i * QKVD * EMB / 2,
                                      qkv_b + i * QKVD, qkv, nullptr, nullptr,
                                      Mtok, QKVD, EMB, nullptr);
        }
        {
            dim3 grid((NTOK + AQT - 1) / AQT, NH, BATCH);
            attn_mma<<<grid, 256>>>(qkv, attnoH, attnoL);
        }
        {
            dim3 grid(EMB / GBN, MtokBlocks);
            gemm_tc<2><<<grid, 256>>>(attnoH, attnoL,
                                      wprojH + (size_t)i * EMB * EMB / 2,
                                      wprojL + (size_t)i * EMB * EMB / 2,
                                      proj_b + i * EMB, t, nullptr, nullptr,
                                      Mtok, EMB, EMB, nullptr);
        }
        ln_split_kernel<<<Mtok, 128>>>(t, ln2_w + i * EMB, ln2_b + i * EMB, hH, hL);
        {
            dim3 grid(MLPD / GBN, MtokBlocks);
            gemm_tc<1><<<grid, 256>>>(hH, hL,
                                      wm1H + (size_t)i * MLPD * EMB / 2,
                                      wm1L + (size_t)i * MLPD * EMB / 2,
                                      mlp_b1 + i * MLPD, nullptr, mlpH, mlpL,
                                      Mtok, MLPD, EMB, nullptr);
        }
        {
            dim3 grid(EMB / GBN, MtokBlocks);
            gemm_tc<2><<<grid, 256>>>(mlpH, mlpL,
                                      wm2H + (size_t)i * EMB * MLPD / 2,
                                      wm2L + (size_t)i * EMB * MLPD / 2,
                                      mlp_b2 + i * EMB, t, nullptr, nullptr,
                                      Mtok, EMB, MLPD, nullptr);
        }
    }

    // 3) head
    head_kernel<<<BATCH, 128>>>(t, norm_w, norm_b, head_w, head_b, out);
}

// round 17
// speedup vs baseline: 37.8979x; 1.0748x over previous
#include <cuda_runtime.h>
#include <cuda_bf16.h>
#include <math.h>
#include <stdint.h>

// ---------------- problem constants ----------------
#define BATCH   2
#define IMG     96
#define PP      8
#define EMB     384
#define NH      8
#define HD      48
#define NL      6
#define MLPD    1536
#define NC      2
#define NPATCH  1728            // (96/8)^3
#define NTOK    1729            // NPATCH + 1
#define PK      512             // P^3 * CIN
#define QKVD    1152            // 3*EMB
#define MTOK    (BATCH * NTOK)  // 3458
#define QKVW    (QKVD / 2)      // 576 words per token
#define HDW     (HD / 2)        // 24 words per head

// ---------------- device scratch (static, allocation-free) ----------------
__device__ unsigned g_patH [BATCH * NPATCH * PK / 2];
__device__ unsigned g_patL [BATCH * NPATCH * PK / 2];
__device__ unsigned g_wconvH[EMB * PK / 2];
__device__ unsigned g_wconvL[EMB * PK / 2];
__device__ unsigned g_wqkvH[NL * QKVD * EMB / 2];
__device__ unsigned g_wqkvL[NL * QKVD * EMB / 2];
__device__ unsigned g_wprojH[NL * EMB * EMB / 2];
__device__ unsigned g_wprojL[NL * EMB * EMB / 2];
__device__ unsigned g_wm1H [NL * MLPD * EMB / 2];
__device__ unsigned g_wm1L [NL * MLPD * EMB / 2];
__device__ unsigned g_wm2H [NL * EMB * MLPD / 2];
__device__ unsigned g_wm2L [NL * EMB * MLPD / 2];
__device__ unsigned g_hH   [MTOK * EMB / 2];
__device__ unsigned g_hL   [MTOK * EMB / 2];
__device__ unsigned g_qkvH [MTOK * QKVW];
__device__ unsigned g_qkvL [MTOK * QKVW];
__device__ unsigned g_attnoH[MTOK * EMB / 2];
__device__ unsigned g_attnoL[MTOK * EMB / 2];
__device__ unsigned g_mlpH [MTOK * MLPD / 2];
__device__ unsigned g_mlpL [MTOK * MLPD / 2];
__device__ float g_t  [MTOK * EMB];

// ---------------- small helpers ----------------
__device__ __forceinline__ void split_pair(float x, float y, unsigned &hi, unsigned &lo) {
    __nv_bfloat16 hx = __float2bfloat16(x);
    __nv_bfloat16 hy = __float2bfloat16(y);
    hi = ((unsigned)__bfloat16_as_ushort(hy) << 16) | (unsigned)__bfloat16_as_ushort(hx);
    float rx = x - __bfloat162float(hx);
    float ry = y - __bfloat162float(hy);
    __nv_bfloat16 lx = __float2bfloat16(rx);
    __nv_bfloat16 ly = __float2bfloat16(ry);
    lo = ((unsigned)__bfloat16_as_ushort(ly) << 16) | (unsigned)__bfloat16_as_ushort(lx);
}

__device__ __forceinline__ void mma_bf16(float c[4], const unsigned a[4],
                                         unsigned b0, unsigned b1) {
    asm volatile(
        "mma.sync.aligned.m16n8k16.row.col.f32.bf16.bf16.f32 "
        "{%0,%1,%2,%3}, {%4,%5,%6,%7}, {%8,%9}, {%0,%1,%2,%3};"
        : "+f"(c[0]), "+f"(c[1]), "+f"(c[2]), "+f"(c[3])
        : "r"(a[0]), "r"(a[1]), "r"(a[2]), "r"(a[3]), "r"(b0), "r"(b1));
}

__device__ __forceinline__ void cp16(void* dst, const void* src, int sz) {
    unsigned d = (unsigned)__cvta_generic_to_shared(dst);
    asm volatile("cp.async.cg.shared.global [%0], [%1], 16, %2;"
                 :: "r"(d), "l"(src), "r"(sz));
}
#define CP_COMMIT() asm volatile("cp.async.commit_group;")
#define CP_WAIT1()  asm volatile("cp.async.wait_group 1;")

// ---------------- generic fp32 -> bf16 hi/lo split (for weights) ----------------
__global__ void split_kernel(const float* __restrict__ src, unsigned* __restrict__ dstH,
                             unsigned* __restrict__ dstL, int npairs) {
    int i = blockIdx.x * blockDim.x + threadIdx.x;
    if (i >= npairs) return;
    float2 v = ((const float2*)src)[i];
    unsigned h, l;
    split_pair(v.x, v.y, h, l);
    dstH[i] = h; dstL[i] = l;
}

// ---------------- patchify: gather + split directly ----------------
__global__ void patchify_kernel(const float* __restrict__ x) {
    int gid = blockIdx.x * blockDim.x + threadIdx.x;
    const int total = BATCH * NPATCH * (PK / 2);
    if (gid >= total) return;
    int pw = gid & (PK / 2 - 1);
    int r  = gid >> 8;
    int e  = pw * 2;
    int b = r / NPATCH;
    int p = r - b * NPATCH;
    int pz = p / 144;
    int py = (p / 12) % 12;
    int px = p % 12;
    int i = e >> 6;
    int j = (e >> 3) & 7;
    int k = e & 7;
    size_t src = (size_t)b * IMG * IMG * IMG
               + (size_t)(pz * PP + i) * IMG * IMG
               + (size_t)(py * PP + j) * IMG
               + (px * PP + k);
    float2 v = *(const float2*)&x[src];
    unsigned h, l;
    split_pair(v.x, v.y, h, l);
    g_patH[(size_t)r * (PK / 2) + pw] = h;
    g_patL[(size_t)r * (PK / 2) + pw] = l;
}

__global__ void cls_init_kernel(const float* __restrict__ cls_token,
                                const float* __restrict__ pos_embed) {
    int gid = blockIdx.x * blockDim.x + threadIdx.x;
    if (gid >= BATCH * EMB) return;
    int b = gid / EMB;
    int e = gid - b * EMB;
    g_t[(size_t)b * NTOK * EMB + e] = cls_token[e] + pos_embed[e];
}

// ---------------- 3xBF16 GEMM, pre-split operands, cp.async double buffer ----------------
// C[M,N] = A[M,K] * W[N,K]^T. EPI: 0 = bias -> split CH/CL (qkv), 1 = bias+GELU -> split,
// 2 = bias+residual -> float C, 3 = patch scatter + pos_embed -> float C
#define GBM 128
#define GBN 128
#define WSTR 12

template<int EPI>
__global__ void __launch_bounds__(256, 2)
gemm_tc(const unsigned* __restrict__ AH, const unsigned* __restrict__ AL,
        const unsigned* __restrict__ WH, const unsigned* __restrict__ WL,
        const float* __restrict__ bias, float* __restrict__ C,
        unsigned* __restrict__ CH, unsigned* __restrict__ CL,
        int M, int N, int K, const float* __restrict__ extra)
{
    __shared__ unsigned sAH[2][GBM * WSTR];
    __shared__ unsigned sAL[2][GBM * WSTR];
    __shared__ unsigned sBH[2][GBN * WSTR];
    __shared__ unsigned sBL[2][GBN * WSTR];

    const int tid  = threadIdx.x;
    const int lane = tid & 31;
    const int warp = tid >> 5;
    const int wm = (warp & 3) * 32;
    const int wn = (warp >> 2) * 64;
    const int bm = blockIdx.y * GBM;
    const int bn = blockIdx.x * GBN;
    const int g  = lane >> 2;
    const int tg = lane & 3;

    const int Kw = K >> 1;
    const int lr = tid >> 1;
    const int lh = (tid & 1) * 4;
    const bool aval = (bm + lr) < M;
    const size_t abase = (size_t)(aval ? bm + lr : 0) * Kw + lh;
    const size_t wbase = (size_t)(bn + lr) * Kw + lh;
    const int asz = aval ? 16 : 0;
    const int sOff = lr * WSTR + lh;

    float c[2][8][4];
    #pragma unroll
    for (int i = 0; i < 2; i++)
        #pragma unroll
        for (int j = 0; j < 8; j++)
            #pragma unroll
            for (int v = 0; v < 4; v++) c[i][j][v] = 0.f;

    const int nIter = K >> 4;

    cp16(&sAH[0][sOff], AH + abase, asz);
    cp16(&sAL[0][sOff], AL + abase, asz);
    cp16(&sBH[0][sOff], WH + wbase, 16);
    cp16(&sBL[0][sOff], WL + wbase, 16);
    CP_COMMIT();

    for (int it = 0; it < nIter; it++) {
        const int st = it & 1;
        if (it + 1 < nIter) {
            const int kw0 = (it + 1) * 8;
            const int so = (st ^ 1);
            cp16(&sAH[so][sOff], AH + abase + kw0, asz);
            cp16(&sAL[so][sOff], AL + abase + kw0, asz);
            cp16(&sBH[so][sOff], WH + wbase + kw0, 16);
            cp16(&sBL[so][sOff], WL + wbase + kw0, 16);
        }
        CP_COMMIT();
        CP_WAIT1();
        __syncthreads();

        const unsigned* aH_s = sAH[st];
        const unsigned* aL_s = sAL[st];
        const unsigned* bH_s = sBH[st];
        const unsigned* bL_s = sBL[st];
        unsigned aH[2][4], aL[2][4];
        #pragma unroll
        for (int i = 0; i < 2; i++) {
            int row = wm + i * 16 + g;
            aH[i][0] = aH_s[row * WSTR + tg];
            aH[i][1] = aH_s[(row + 8) * WSTR + tg];
            aH[i][2] = aH_s[row * WSTR + tg + 4];
            aH[i][3] = aH_s[(row + 8) * WSTR + tg + 4];
            aL[i][0] = aL_s[row * WSTR + tg];
            aL[i][1] = aL_s[(row + 8) * WSTR + tg];
            aL[i][2] = aL_s[row * WSTR + tg + 4];
            aL[i][3] = aL_s[(row + 8) * WSTR + tg + 4];
        }
        #pragma unroll
        for (int j = 0; j < 8; j++) {
            int col = wn + j * 8 + g;
            unsigned bh0 = bH_s[col * WSTR + tg];
            unsigned bh1 = bH_s[col * WSTR + tg + 4];
            unsigned bl0 = bL_s[col * WSTR + tg];
            unsigned bl1 = bL_s[col * WSTR + tg + 4];
            #pragma unroll
            for (int i = 0; i < 2; i++) {
                mma_bf16(c[i][j], aH[i], bh0, bh1);
                mma_bf16(c[i][j], aH[i], bl0, bl1);
                mma_bf16(c[i][j], aL[i], bh0, bh1);
            }
        }
        __syncthreads();
    }

    #pragma unroll
    for (int i = 0; i < 2; i++) {
        #pragma unroll
        for (int half = 0; half < 2; half++) {
            int r = bm + wm + i * 16 + g + half * 8;
            if (r >= M) continue;
            #pragma unroll
            for (int j = 0; j < 8; j++) {
                int col = bn + wn + j * 8 + tg * 2;
                float v0 = c[i][j][half * 2 + 0] + bias[col];
                float v1 = c[i][j][half * 2 + 1] + bias[col + 1];
                if (EPI == 0) {           // bias -> split store (qkv)
                    unsigned hh, ll;
                    split_pair(v0, v1, hh, ll);
                    size_t w = ((size_t)r * N + col) >> 1;
                    CH[w] = hh; CL[w] = ll;
                } else if (EPI == 1) {    // bias + GELU -> split store
                    float g0 = 0.5f * v0 * (1.0f + erff(v0 * 0.70710678118654752f));
                    float g1 = 0.5f * v1 * (1.0f + erff(v1 * 0.70710678118654752f));
                    unsigned hh, ll;
                    split_pair(g0, g1, hh, ll);
                    size_t w = ((size_t)r * N + col) >> 1;
                    CH[w] = hh; CL[w] = ll;
                } else if (EPI == 2) {    // bias + residual add -> float
                    size_t o = (size_t)r * N + col;
                    float2 old = *(float2*)&C[o];
                    *(float2*)&C[o] = make_float2(old.x + v0, old.y + v1);
                } else {                  // patch scatter + pos_embed -> float
                    int b = r / NPATCH;
                    int p = r - b * NPATCH;
                    size_t o = ((size_t)b * NTOK + 1 + p) * EMB + col;
                    C[o]     = v0 + extra[(size_t)(1 + p) * EMB + col];
                    C[o + 1] = v1 + extra[(size_t)(1 + p) * EMB + col + 1];
                }
            }
        }
    }
}

// ---------------- LayerNorm -> split bf16 hi/lo output ----------------
__global__ void ln_split_kernel(const float* __restrict__ x, const float* __restrict__ w,
                                const float* __restrict__ bvec,
                                unsigned* __restrict__ yH, unsigned* __restrict__ yL) {
    const int row = blockIdx.x;
    const float* xr = x + (size_t)row * EMB;
    const int tid = threadIdx.x;
    float s = 0.f, s2 = 0.f;
    #pragma unroll
    for (int e = tid; e < EMB; e += 128) {
        float v = xr[e];
        s += v; s2 += v * v;
    }
    #pragma unroll
    for (int o = 16; o; o >>= 1) {
        s  += __shfl_xor_sync(0xffffffffu, s,  o);
        s2 += __shfl_xor_sync(0xffffffffu, s2, o);
    }
    __shared__ float r1[4], r2[4];
    if ((tid & 31) == 0) { r1[tid >> 5] = s; r2[tid >> 5] = s2; }
    __syncthreads();
    float S  = r1[0] + r1[1] + r1[2] + r1[3];
    float S2 = r2[0] + r2[1] + r2[2] + r2[3];
    float mu = S * (1.0f / EMB);
    float var = S2 * (1.0f / EMB) - mu * mu;
    float rs = rsqrtf(var + 1e-5f);
    #pragma unroll
    for (int p = tid; p < EMB / 2; p += 128) {
        int e = p * 2;
        float v0 = (xr[e]     - mu) * rs * w[e]     + bvec[e];
        float v1 = (xr[e + 1] - mu) * rs * w[e + 1] + bvec[e + 1];
        unsigned hh, ll;
        split_pair(v0, v1, hh, ll);
        yH[(size_t)row * (EMB / 2) + p] = hh;
        yL[(size_t)row * (EMB / 2) + p] = ll;
    }
}

// ---------------- tensor-core flash attention (3xBF16, pre-split QKV) ----------------
// Block: 8 warps x 16 queries = 128 q/block, one (b,h). Q frags direct from split words;
// K tile = pure word copies; V tile = half-word transpose scatter (no conversions).
#define AQT 128
#define AKT 48
#define KSTR 28
#define VSTR 28

__global__ void __launch_bounds__(256, 2)
attn_mma(const unsigned* __restrict__ qkvH, const unsigned* __restrict__ qkvL,
         unsigned* __restrict__ outH, unsigned* __restrict__ outL) {
    __shared__ unsigned ksH[AKT * KSTR], ksL[AKT * KSTR];
    __shared__ unsigned vsH[HD * VSTR],  vsL[HD * VSTR];

    const int tid  = threadIdx.x;
    const int lane = tid & 31;
    const int warp = tid >> 5;
    const int g  = lane >> 2;
    const int tg = lane & 3;
    const int h = blockIdx.y, b = blockIdx.z;
    const int qbase = blockIdx.x * AQT;
    const float scale = 0.14433756729740643f;   // 1/sqrt(48)

    // ---- persistent Q fragments: direct loads from pre-split words ----
    unsigned qfH[3][4], qfL[3][4];
    {
        const int r0q = qbase + 16 * warp + g;
        #pragma unroll
        for (int ks = 0; ks < 3; ks++) {
            #pragma unroll
            for (int sl = 0; sl < 4; sl++) {
                int r = r0q + (sl & 1) * 8;
                int widx = 8 * ks + tg + (sl >> 1) * 4;
                if (r < NTOK) {
                    size_t w = (size_t)(b * NTOK + r) * QKVW + h * HDW + widx;
                    qfH[ks][sl] = qkvH[w];
                    qfL[ks][sl] = qkvL[w];
                } else {
                    qfH[ks][sl] = 0u; qfL[ks][sl] = 0u;
                }
            }
        }
    }

    float acc[6][4];
    #pragma unroll
    for (int n = 0; n < 6; n++)
        #pragma unroll
        for (int v = 0; v < 4; v++) acc[n][v] = 0.f;
    float m0 = -1e30f, m1 = -1e30f, l0 = 0.f, l1 = 0.f;

    const int ntiles = (NTOK + AKT - 1) / AKT;   // 37
    for (int t0 = 0; t0 < ntiles; t0++) {
        const int kbase = t0 * AKT;
        __syncthreads();
        // ---- load K (word copies) and V (transpose, half-word scatter) ----
        #pragma unroll
        for (int lp = 0; lp < 3; lp++) {
            int idx = tid + 256 * lp;
            if (idx < AKT * 12) {
                int row = idx / 12, c4 = idx % 12;
                int gk = kbase + row;
                uint2 kh = make_uint2(0u, 0u), kl = kh, vh = kh, vl = kh;
                if (gk < NTOK) {
                    size_t base = (size_t)(b * NTOK + gk) * QKVW + h * HDW + 2 * c4;
                    kh = *(const uint2*)&qkvH[base + EMB / 2];
                    kl = *(const uint2*)&qkvL[base + EMB / 2];
                    vh = *(const uint2*)&qkvH[base + EMB];
                    vl = *(const uint2*)&qkvL[base + EMB];
                }
                ksH[row * KSTR + 2 * c4]     = kh.x;
                ksH[row * KSTR + 2 * c4 + 1] = kh.y;
                ksL[row * KSTR + 2 * c4]     = kl.x;
                ksL[row * KSTR + 2 * c4 + 1] = kl.y;
                unsigned short* vbh = (unsigned short*)vsH;
                unsigned short* vbl = (unsigned short*)vsL;
                int d0 = 4 * c4;
                vbh[(d0 + 0) * (VSTR * 2) + row] = (unsigned short)(vh.x & 0xFFFF);
                vbh[(d0 + 1) * (VSTR * 2) + row] = (unsigned short)(vh.x >> 16);
                vbh[(d0 + 2) * (VSTR * 2) + row] = (unsigned short)(vh.y & 0xFFFF);
                vbh[(d0 + 3) * (VSTR * 2) + row] = (unsigned short)(vh.y >> 16);
                vbl[(d0 + 0) * (VSTR * 2) + row] = (unsigned short)(vl.x & 0xFFFF);
                vbl[(d0 + 1) * (VSTR * 2) + row] = (unsigned short)(vl.x >> 16);
                vbl[(d0 + 2) * (VSTR * 2) + row] = (unsigned short)(vl.y & 0xFFFF);
                vbl[(d0 + 3) * (VSTR * 2) + row] = (unsigned short)(vl.y >> 16);
            }
        }
        __syncthreads();

        // ---- QK scores ----
        float s[6][4];
        #pragma unroll
        for (int j = 0; j < 6; j++)
            #pragma unroll
            for (int v = 0; v < 4; v++) s[j][v] = 0.f;
        #pragma unroll
        for (int j = 0; j < 6; j++) {
            #pragma unroll
            for (int ks = 0; ks < 3; ks++) {
                int o = (8 * j + g) * KSTR + 8 * ks + tg;
                unsigned bh0 = ksH[o], bh1 = ksH[o + 4];
                unsigned bl0 = ksL[o], bl1 = ksL[o + 4];
                mma_bf16(s[j], qfH[ks], bh0, bh1);
                mma_bf16(s[j], qfH[ks], bl0, bl1);
                mma_bf16(s[j], qfL[ks], bh0, bh1);
            }
        }
        // scale then mask
        #pragma unroll
        for (int j = 0; j < 6; j++) {
            s[j][0] *= scale; s[j][1] *= scale; s[j][2] *= scale; s[j][3] *= scale;
        }
        if (kbase + AKT > NTOK) {
            #pragma unroll
            for (int j = 0; j < 6; j++) {
                int k0 = kbase + 8 * j + 2 * tg;
                if (k0     >= NTOK) { s[j][0] = -1e30f; s[j][2] = -1e30f; }
                if (k0 + 1 >= NTOK) { s[j][1] = -1e30f; s[j][3] = -1e30f; }
            }
        }
        // ---- online softmax (rows g and g+8) ----
        float mx0 = -1e30f, mx1 = -1e30f;
        #pragma unroll
        for (int j = 0; j < 6; j++) {
            mx0 = fmaxf(mx0, fmaxf(s[j][0], s[j][1]));
            mx1 = fmaxf(mx1, fmaxf(s[j][2], s[j][3]));
        }
        mx0 = fmaxf(mx0, __shfl_xor_sync(0xffffffffu, mx0, 1));
        mx0 = fmaxf(mx0, __shfl_xor_sync(0xffffffffu, mx0, 2));
        mx1 = fmaxf(mx1, __shfl_xor_sync(0xffffffffu, mx1, 1));
        mx1 = fmaxf(mx1, __shfl_xor_sync(0xffffffffu, mx1, 2));
        float mn0 = fmaxf(m0, mx0), mn1 = fmaxf(m1, mx1);
        float a0 = __expf(m0 - mn0), a1 = __expf(m1 - mn1);
        unsigned ph0[6], pl0[6], ph1[6], pl1[6];
        float ps0 = 0.f, ps1 = 0.f;
        #pragma unroll
        for (int j = 0; j < 6; j++) {
            float p0 = __expf(s[j][0] - mn0);
            float p1 = __expf(s[j][1] - mn0);
            float p2 = __expf(s[j][2] - mn1);
            float p3 = __expf(s[j][3] - mn1);
            ps0 += p0 + p1; ps1 += p2 + p3;
            split_pair(p0, p1, ph0[j], pl0[j]);
            split_pair(p2, p3, ph1[j], pl1[j]);
        }
        ps0 += __shfl_xor_sync(0xffffffffu, ps0, 1);
        ps0 += __shfl_xor_sync(0xffffffffu, ps0, 2);
        ps1 += __shfl_xor_sync(0xffffffffu, ps1, 1);
        ps1 += __shfl_xor_sync(0xffffffffu, ps1, 2);
        l0 = l0 * a0 + ps0;
        l1 = l1 * a1 + ps1;
        m0 = mn0; m1 = mn1;
        #pragma unroll
        for (int n = 0; n < 6; n++) {
            acc[n][0] *= a0; acc[n][1] *= a0;
            acc[n][2] *= a1; acc[n][3] *= a1;
        }
        // ---- PV ----
        #pragma unroll
        for (int ks = 0; ks < 3; ks++) {
            unsigned aPh[4] = { ph0[2 * ks], ph1[2 * ks], ph0[2 * ks + 1], ph1[2 * ks + 1] };
            unsigned aPl[4] = { pl0[2 * ks], pl1[2 * ks], pl0[2 * ks + 1], pl1[2 * ks + 1] };
            #pragma unroll
            for (int n = 0; n < 6; n++) {
                int o = (8 * n + g) * VSTR + 8 * ks + tg;
                unsigned bh0 = vsH[o], bh1 = vsH[o + 4];
                unsigned bl0 = vsL[o], bl1 = vsL[o + 4];
                mma_bf16(acc[n], aPh, bh0, bh1);
                mma_bf16(acc[n], aPh, bl0, bl1);
                mma_bf16(acc[n], aPl, bh0, bh1);
            }
        }
    }

    // ---- epilogue: normalize + split-store ----
    const int r0 = qbase + 16 * warp + g;
    const int r1 = r0 + 8;
    float inv0 = 1.0f / l0, inv1 = 1.0f / l1;
    if (r0 < NTOK) {
        size_t wb = (size_t)(b * NTOK + r0) * (EMB / 2) + 24 * h + tg;
        #pragma unroll
        for (int n = 0; n < 6; n++) {
            unsigned hh, ll;
            split_pair(acc[n][0] * inv0, acc[n][1] * inv0, hh, ll);
            outH[wb + 4 * n] = hh; outL[wb + 4 * n] = ll;
        }
    }
    if (r1 < NTOK) {
        size_t wb = (size_t)(b * NTOK + r1) * (EMB / 2) + 24 * h + tg;
        #pragma unroll
        for (int n = 0; n < 6; n++) {
            unsigned hh, ll;
            split_pair(acc[n][2] * inv1, acc[n][3] * inv1, hh, ll);
            outH[wb + 4 * n] = hh; outL[wb + 4 * n] = ll;
        }
    }
}

// ---------------- final LN(cls) + head ----------------
__global__ void head_kernel(const float* __restrict__ t, const float* __restrict__ nw,
                            const float* __restrict__ nb, const float* __restrict__ hw,
                            const float* __restrict__ hb, float* __restrict__ out) {
    const int b = blockIdx.x;
    const float* xr = t + (size_t)b * NTOK * EMB;
    const int tid = threadIdx.x;
    float s = 0.f, s2 = 0.f;
    for (int e = tid; e < EMB; e += 128) { float v = xr[e]; s += v; s2 += v * v; }
    #pragma unroll
    for (int o = 16; o; o >>= 1) {
        s  += __shfl_xor_sync(0xffffffffu, s,  o);
        s2 += __shfl_xor_sync(0xffffffffu, s2, o);
    }
    __shared__ float r1[4], r2[4], rd0[4], rd1[4];
    if ((tid & 31) == 0) { r1[tid >> 5] = s; r2[tid >> 5] = s2; }
    __syncthreads();
    float S  = r1[0] + r1[1] + r1[2] + r1[3];
    float S2 = r2[0] + r2[1] + r2[2] + r2[3];
    float mu = S * (1.0f / EMB);
    float rs = rsqrtf(S2 * (1.0f / EMB) - mu * mu + 1e-5f);
    float d0 = 0.f, d1 = 0.f;
    for (int e = tid; e < EMB; e += 128) {
        float nv = (xr[e] - mu) * rs * nw[e] + nb[e];
        d0 += nv * hw[e];
        d1 += nv * hw[EMB + e];
    }
    #pragma unroll
    for (int o = 16; o; o >>= 1) {
        d0 += __shfl_xor_sync(0xffffffffu, d0, o);
        d1 += __shfl_xor_sync(0xffffffffu, d1, o);
    }
    if ((tid & 31) == 0) { rd0[tid >> 5] = d0; rd1[tid >> 5] = d1; }
    __syncthreads();
    if (tid == 0) {
        out[b * NC + 0] = rd0[0] + rd0[1] + rd0[2] + rd0[3] + hb[0];
        out[b * NC + 1] = rd1[0] + rd1[1] + rd1[2] + rd1[3] + hb[1];
    }
}

// ---------------- host orchestration ----------------
extern "C" void kernel_launch(void* const* d_in, const int* in_sizes, int n_in,
                              void* d_out, int out_size) {
    const float* x         = (const float*)d_in[0];
    const float* conv_w    = (const float*)d_in[1];
    const float* conv_b    = (const float*)d_in[2];
    const float* cls_token = (const float*)d_in[3];
    const float* pos_embed = (const float*)d_in[4];
    const float* ln1_w     = (const float*)d_in[5];
    const float* ln1_b     = (const float*)d_in[6];
    const float* qkv_w     = (const float*)d_in[7];
    const float* qkv_b     = (const float*)d_in[8];
    const float* proj_w    = (const float*)d_in[9];
    const float* proj_b    = (const float*)d_in[10];
    const float* ln2_w     = (const float*)d_in[11];
    const float* ln2_b     = (const float*)d_in[12];
    const float* mlp_w1    = (const float*)d_in[13];
    const float* mlp_b1    = (const float*)d_in[14];
    const float* mlp_w2    = (const float*)d_in[15];
    const float* mlp_b2    = (const float*)d_in[16];
    const float* norm_w    = (const float*)d_in[17];
    const float* norm_b    = (const float*)d_in[18];
    const float* head_w    = (const float*)d_in[19];
    const float* head_b    = (const float*)d_in[20];
    float* out = (float*)d_out;

    unsigned *patH, *patL, *wconvH, *wconvL, *wqkvH, *wqkvL, *wprojH, *wprojL;
    unsigned *wm1H, *wm1L, *wm2H, *wm2L, *hH, *hL, *qkvH, *qkvL, *attnoH, *attnoL, *mlpH, *mlpL;
    float *t;
    cudaGetSymbolAddress((void**)&patH,   g_patH);
    cudaGetSymbolAddress((void**)&patL,   g_patL);
    cudaGetSymbolAddress((void**)&wconvH, g_wconvH);
    cudaGetSymbolAddress((void**)&wconvL, g_wconvL);
    cudaGetSymbolAddress((void**)&wqkvH,  g_wqkvH);
    cudaGetSymbolAddress((void**)&wqkvL,  g_wqkvL);
    cudaGetSymbolAddress((void**)&wprojH, g_wprojH);
    cudaGetSymbolAddress((void**)&wprojL, g_wprojL);
    cudaGetSymbolAddress((void**)&wm1H,   g_wm1H);
    cudaGetSymbolAddress((void**)&wm1L,   g_wm1L);
    cudaGetSymbolAddress((void**)&wm2H,   g_wm2H);
    cudaGetSymbolAddress((void**)&wm2L,   g_wm2L);
    cudaGetSymbolAddress((void**)&hH,     g_hH);
    cudaGetSymbolAddress((void**)&hL,     g_hL);
    cudaGetSymbolAddress((void**)&qkvH,   g_qkvH);
    cudaGetSymbolAddress((void**)&qkvL,   g_qkvL);
    cudaGetSymbolAddress((void**)&attnoH, g_attnoH);
    cudaGetSymbolAddress((void**)&attnoL, g_attnoL);
    cudaGetSymbolAddress((void**)&mlpH,   g_mlpH);
    cudaGetSymbolAddress((void**)&mlpL,   g_mlpL);
    cudaGetSymbolAddress((void**)&t,      g_t);

    const int Mtok = MTOK;
    const int Mpat = BATCH * NPATCH;
    const int MtokBlocks = (Mtok + GBM - 1) / GBM;  // 28

    // 0) weight splits
    {
        int np;
        np = EMB * PK / 2;             split_kernel<<<(np + 255) / 256, 256>>>(conv_w, wconvH, wconvL, np);
        np = NL * QKVD * EMB / 2;      split_kernel<<<(np + 255) / 256, 256>>>(qkv_w,  wqkvH,  wqkvL,  np);
        np = NL * EMB * EMB / 2;       split_kernel<<<(np + 255) / 256, 256>>>(proj_w, wprojH, wprojL, np);
        np = NL * MLPD * EMB / 2;      split_kernel<<<(np + 255) / 256, 256>>>(mlp_w1, wm1H,   wm1L,   np);
        np = NL * EMB * MLPD / 2;      split_kernel<<<(np + 255) / 256, 256>>>(mlp_w2, wm2H,   wm2L,   np);
    }

    // 1) patchify(+split) + patch-embed GEMM + cls
    {
        int total = BATCH * NPATCH * (PK / 2);
        patchify_kernel<<<(total + 255) / 256, 256>>>(x);
        dim3 grid(EMB / GBN, Mpat / GBM);
        gemm_tc<3><<<grid, 256>>>(patH, patL, wconvH, wconvL, conv_b, t, nullptr, nullptr,
                                  Mpat, EMB, PK, pos_embed);
        cls_init_kernel<<<(BATCH * EMB + 255) / 256, 256>>>(cls_token, pos_embed);
    }

    // 2) transformer layers
    for (int i = 0; i < NL; i++) {
        ln_split_kernel<<<Mtok, 128>>>(t, ln1_w + i * EMB, ln1_b + i * EMB, hH, hL);
        {
            dim3 grid(QKVD / GBN, MtokBlocks);
            gemm_tc<0><<<grid, 256>>>(hH, hL,
                                      wqkvH + (size_t)i * QKVD * EMB / 2,
                                      wqkvL + (size_t)i * QKVD * EMB / 2,
                                      qkv_b + i * QKVD, nullptr, qkvH, qkvL,
                                      Mtok, QKVD, EMB, nullptr);
        }
        {
            dim3 grid((NTOK + AQT - 1) / AQT, NH, BATCH);
            attn_mma<<<grid, 256>>>(qkvH, qkvL, attnoH, attnoL);
        }
        {
            dim3 grid(EMB / GBN, MtokBlocks);
            gemm_tc<2><<<grid, 256>>>(attnoH, attnoL,
                                      wprojH + (size_t)i * EMB * EMB / 2,
                                      wprojL + (size_t)i * EMB * EMB / 2,
                                      proj_b + i * EMB, t, nullptr, nullptr,
                                      Mtok, EMB, EMB, nullptr);
        }
        ln_split_kernel<<<Mtok, 128>>>(t, ln2_w + i * EMB, ln2_b + i * EMB, hH, hL);
        {
            dim3 grid(MLPD / GBN, MtokBlocks);
            gemm_tc<1><<<grid, 256>>>(hH, hL,
                                      wm1H + (size_t)i * MLPD * EMB / 2,
                                      wm1L + (size_t)i * MLPD * EMB / 2,
                                      mlp_b1 + i * MLPD, nullptr, mlpH, mlpL,
                                      Mtok, MLPD, EMB, nullptr);
        }
        {
            dim3 grid(EMB / GBN, MtokBlocks);
            gemm_tc<2><<<grid, 256>>>(mlpH, mlpL,
                                      wm2H + (size_t)i * EMB * MLPD / 2,
                                      wm2L + (size_t)i * EMB * MLPD / 2,
                                      mlp_b2 + i * EMB, t, nullptr, nullptr,
                                      Mtok, EMB, MLPD, nullptr);
        }
    }

    // 3) head
    head_kernel<<<BATCH, 128>>>(t, norm_w, norm_b, head_w, head_b, out);
}